// round 8
// baseline (speedup 1.0000x reference)
#include <cuda_runtime.h>
#include <math.h>
#include <stdint.h>

#define BATCH 8192
#define NN 4096
#define LDB 68           // padded stride (floats), float4-aligned
#define EPSF 1e-8f
#define SKIP_TAU 4e-6f

#define K0_BLOCKS 256
#define K0_NB 32
#define K2_BLOCKS 2048
#define K2_NB 4
#define SWEEPS_BATCH 7
#define SWEEPS_SMALL 8
#define SWEEPS_TS 8

// ---------------- device scratch ----------------
__device__ __align__(256) float g_partial_mean[(size_t)K0_BLOCKS * NN];
__device__ __align__(256) float g_mean[NN];
__device__ __align__(256) float g_s[NN];
__device__ __align__(256) float g_si[NN];
__device__ __align__(256) float g_gsqrt[NN];
__device__ __align__(256) float g_W[NN];
__device__ __align__(256) float g_WT[NN];
__device__ __align__(256) float g_partial_t[(size_t)K2_BLOCKS * NN];
__device__ __align__(256) float g_tmean[NN];

// ---------------- packed f32x2 helpers ----------------
typedef unsigned long long u64;
__device__ __forceinline__ u64 pk2(float x, float y) {
    u64 r; asm("mov.b64 %0,{%1,%2};" : "=l"(r) : "f"(x), "f"(y)); return r;
}
__device__ __forceinline__ void up2(u64 v, float& x, float& y) {
    asm("mov.b64 {%0,%1},%2;" : "=f"(x), "=f"(y) : "l"(v));
}
__device__ __forceinline__ u64 fma2(u64 a, u64 b, u64 c) {
    u64 d; asm("fma.rn.f32x2 %0,%1,%2,%3;" : "=l"(d) : "l"(a), "l"(b), "l"(c)); return d;
}
__device__ __forceinline__ u64 mul2(u64 a, u64 b) {
    u64 d; asm("mul.rn.f32x2 %0,%1,%2;" : "=l"(d) : "l"(a), "l"(b)); return d;
}

// ---------------- tile movement (256 threads) ----------------
__device__ __forceinline__ void load_tile(const float* __restrict__ g, float* __restrict__ s) {
    for (int i = threadIdx.x; i < 1024; i += 256) {
        int r = i >> 4, c4 = (i & 15) << 2;
        *(float4*)&s[r * LDB + c4] = *(const float4*)&g[(r << 6) + c4];
    }
}
__device__ __forceinline__ void store_tile(const float* __restrict__ s, float* __restrict__ g) {
    for (int i = threadIdx.x; i < 1024; i += 256) {
        int r = i >> 4, c4 = (i & 15) << 2;
        *(float4*)&g[(r << 6) + c4] = *(const float4*)&s[r * LDB + c4];
    }
}

// ---------------- 4x4 register-tiled matmul: C = A @ B (256 threads) ----------------
__device__ __forceinline__ void mm64_t4(const float* __restrict__ A, const float* __restrict__ B,
                                        float* __restrict__ C, int cstride) {
    const int r0 = (threadIdx.x >> 4) << 2;
    const int c0 = (threadIdx.x & 15) << 2;
    u64 acc[8];
#pragma unroll
    for (int i = 0; i < 8; ++i) acc[i] = 0ull;
#pragma unroll 4
    for (int k = 0; k < 64; ++k) {
        float a0 = A[r0 * LDB + k],       a1 = A[(r0 + 1) * LDB + k];
        float a2 = A[(r0 + 2) * LDB + k], a3 = A[(r0 + 3) * LDB + k];
        ulonglong2 b = *(const ulonglong2*)&B[k * LDB + c0];
        u64 p;
        p = pk2(a0, a0); acc[0] = fma2(p, b.x, acc[0]); acc[1] = fma2(p, b.y, acc[1]);
        p = pk2(a1, a1); acc[2] = fma2(p, b.x, acc[2]); acc[3] = fma2(p, b.y, acc[3]);
        p = pk2(a2, a2); acc[4] = fma2(p, b.x, acc[4]); acc[5] = fma2(p, b.y, acc[5]);
        p = pk2(a3, a3); acc[6] = fma2(p, b.x, acc[6]); acc[7] = fma2(p, b.y, acc[7]);
    }
#pragma unroll
    for (int i = 0; i < 4; ++i)
        *(ulonglong2*)&C[(r0 + i) * cstride + c0] = make_ulonglong2(acc[2 * i], acc[2 * i + 1]);
}

// out[r][c] = sum_j Bs[j][r] * B[j][c], 4x4 tiles.
__device__ __forceinline__ void gram_t4(const float* __restrict__ Bs, const float* __restrict__ B,
                                        float* __restrict__ out, int ostride) {
    const int r0 = (threadIdx.x >> 4) << 2;
    const int c0 = (threadIdx.x & 15) << 2;
    u64 acc[8];
#pragma unroll
    for (int i = 0; i < 8; ++i) acc[i] = 0ull;
#pragma unroll 4
    for (int j = 0; j < 64; ++j) {
        float4 u = *(const float4*)&Bs[j * LDB + r0];
        ulonglong2 b = *(const ulonglong2*)&B[j * LDB + c0];
        u64 p;
        p = pk2(u.x, u.x); acc[0] = fma2(p, b.x, acc[0]); acc[1] = fma2(p, b.y, acc[1]);
        p = pk2(u.y, u.y); acc[2] = fma2(p, b.x, acc[2]); acc[3] = fma2(p, b.y, acc[3]);
        p = pk2(u.z, u.z); acc[4] = fma2(p, b.x, acc[4]); acc[5] = fma2(p, b.y, acc[5]);
        p = pk2(u.w, u.w); acc[6] = fma2(p, b.x, acc[6]); acc[7] = fma2(p, b.y, acc[7]);
    }
#pragma unroll
    for (int i = 0; i < 4; ++i)
        *(ulonglong2*)&out[(r0 + i) * ostride + c0] = make_ulonglong2(acc[2 * i], acc[2 * i + 1]);
}

__device__ __forceinline__ float colnrm2(const float* __restrict__ B, int j, int seg, float4 v[4]) {
    const float4* c = (const float4*)(B + j * LDB + (seg << 4));
    v[0] = c[0]; v[1] = c[1]; v[2] = c[2]; v[3] = c[3];
    float n = v[0].x * v[0].x;
    n = fmaf(v[0].y, v[0].y, n); n = fmaf(v[0].z, v[0].z, n); n = fmaf(v[0].w, v[0].w, n);
    n = fmaf(v[1].x, v[1].x, n); n = fmaf(v[1].y, v[1].y, n); n = fmaf(v[1].z, v[1].z, n); n = fmaf(v[1].w, v[1].w, n);
    n = fmaf(v[2].x, v[2].x, n); n = fmaf(v[2].y, v[2].y, n); n = fmaf(v[2].z, v[2].z, n); n = fmaf(v[2].w, v[2].w, n);
    n = fmaf(v[3].x, v[3].x, n); n = fmaf(v[3].y, v[3].y, n); n = fmaf(v[3].z, v[3].z, n); n = fmaf(v[3].w, v[3].w, n);
    n += __shfl_xor_sync(0xffffffffu, n, 1);
    n += __shfl_xor_sync(0xffffffffu, n, 2);
    return n;
}

__device__ __forceinline__ void scale_store(float* __restrict__ D, int j, int seg,
                                            const float4 v[4], float f) {
    float4* d = (float4*)(D + j * LDB + (seg << 4));
    d[0] = make_float4(f * v[0].x, f * v[0].y, f * v[0].z, f * v[0].w);
    d[1] = make_float4(f * v[1].x, f * v[1].y, f * v[1].z, f * v[1].w);
    d[2] = make_float4(f * v[2].x, f * v[2].y, f * v[2].z, f * v[2].w);
    d[3] = make_float4(f * v[3].x, f * v[3].y, f * v[3].z, f * v[3].w);
}

// ---------------- one-sided Jacobi: tracked norms + skip + early sweep exit ----------------
// Octet (tid>>3) owns pair k; lane sub=tid&7 handles rows [4s,4s+4)+[32+4s,..)
// -> conflict-free LDS/STS.128. Rotations with |apq| <= SKIP_TAU*sqrt(app*aqq)
// are skipped; a sweep with zero rotations terminates the solve (flag handshake
// is barrier-ordered: reset before sweep-start sync, read before post-sweep sync).
__device__ void jacobi_onesided(float* __restrict__ B, float* __restrict__ nbuf,
                                int* __restrict__ flag, int sweeps) {
    const int tid = threadIdx.x;
    const int k = tid >> 3;
    const int o0 = (tid & 7) << 2;
    const int o1 = 32 + o0;
    const int jn = tid >> 2, segn = tid & 3;
    for (int sw = 0; sw < sweeps; ++sw) {
        {
            float4 v[4];
            float n = colnrm2(B, jn, segn, v);
            if (segn == 0) nbuf[jn] = n;
        }
        if (tid == 0) *flag = 0;
        __syncthreads();
        int p = (k == 0) ? 0 : k;
        int q = 63 - k;
        for (int rr = 0; rr < 63; ++rr) {
            float* bp = B + p * LDB;
            float* bq = B + q * LDB;
            ulonglong2 P0 = *(ulonglong2*)(bp + o0), P1 = *(ulonglong2*)(bp + o1);
            ulonglong2 Q0 = *(ulonglong2*)(bq + o0), Q1 = *(ulonglong2*)(bq + o1);
            u64 spq = mul2(P0.x, Q0.x);
            spq = fma2(P0.y, Q0.y, spq); spq = fma2(P1.x, Q1.x, spq); spq = fma2(P1.y, Q1.y, spq);
            float a0, a1;
            up2(spq, a0, a1);
            float apq = a0 + a1;
            apq += __shfl_xor_sync(0xffffffffu, apq, 1);
            apq += __shfl_xor_sync(0xffffffffu, apq, 2);
            apq += __shfl_xor_sync(0xffffffffu, apq, 4);
            float app = nbuf[p], aqq = nbuf[q];
            if (apq * apq > SKIP_TAU * SKIP_TAU * app * aqq) {
                float zeta = (aqq - app) / (2.0f * apq);
                float t = copysignf(1.0f, zeta) / (fabsf(zeta) + sqrtf(fmaf(zeta, zeta, 1.0f)));
                float c = rsqrtf(fmaf(t, t, 1.0f));
                float s = t * c;
                u64 c2 = pk2(c, c), s2 = pk2(s, s), ns2 = pk2(-s, -s);
                ulonglong2 NP0, NP1, NQ0, NQ1;
                NP0.x = fma2(c2, P0.x, mul2(ns2, Q0.x));
                NP0.y = fma2(c2, P0.y, mul2(ns2, Q0.y));
                NP1.x = fma2(c2, P1.x, mul2(ns2, Q1.x));
                NP1.y = fma2(c2, P1.y, mul2(ns2, Q1.y));
                NQ0.x = fma2(s2, P0.x, mul2(c2, Q0.x));
                NQ0.y = fma2(s2, P0.y, mul2(c2, Q0.y));
                NQ1.x = fma2(s2, P1.x, mul2(c2, Q1.x));
                NQ1.y = fma2(s2, P1.y, mul2(c2, Q1.y));
                *(ulonglong2*)(bp + o0) = NP0; *(ulonglong2*)(bp + o1) = NP1;
                *(ulonglong2*)(bq + o0) = NQ0; *(ulonglong2*)(bq + o1) = NQ1;
                if ((tid & 7) == 0) {
                    float d = t * apq;
                    nbuf[p] = app - d;
                    nbuf[q] = aqq + d;
                    *flag = 1;
                }
            }
            if (k) p = (p == 63) ? 1 : p + 1;
            q = (q == 63) ? 1 : q + 1;
            __syncthreads();
        }
        int f = *flag;
        __syncthreads();
        if (!f) break;
    }
}

// ---------------- two-sided Jacobi (only for indefinite tmean) ----------------
__device__ void jacobi_twosided(float* __restrict__ A, float* __restrict__ VT,
                                float* cbuf, float* sbuf, int sweeps) {
    const int tid = threadIdx.x;
    for (int idx = tid; idx < NN; idx += 256) {
        int r = idx >> 6, c = idx & 63;
        VT[r * LDB + c] = (r == c) ? 1.f : 0.f;
    }
    __syncthreads();
    for (int sw = 0; sw < sweeps; ++sw) {
        for (int rr = 0; rr < 63; ++rr) {
            if (tid < 32) {
                int p = (tid == 0) ? 0 : 1 + (tid - 1 + rr) % 63;
                int q = 1 + (62 - tid + rr) % 63;
                float app = A[p * LDB + p], aqq = A[q * LDB + q], apq = A[p * LDB + q];
                float c, s;
                if (fabsf(apq) > 1e-30f) {
                    float th = 0.5f * (aqq - app) / apq;
                    float t = copysignf(1.f, th) / (fabsf(th) + sqrtf(fmaf(th, th, 1.f)));
                    c = rsqrtf(fmaf(t, t, 1.f)); s = t * c;
                } else { c = 1.f; s = 0.f; }
                cbuf[tid] = c; sbuf[tid] = s;
            }
            __syncthreads();
            for (int u = tid; u < 1536; u += 256) {
                if (u < 1024) {
                    int ki = u & 31, kj = u >> 5;
                    int pi = (ki == 0) ? 0 : 1 + (ki - 1 + rr) % 63, qi = 1 + (62 - ki + rr) % 63;
                    int pj = (kj == 0) ? 0 : 1 + (kj - 1 + rr) % 63, qj = 1 + (62 - kj + rr) % 63;
                    float ci = cbuf[ki], si = sbuf[ki], cj = cbuf[kj], sj = sbuf[kj];
                    float a00 = A[pi * LDB + pj], a01 = A[pi * LDB + qj];
                    float a10 = A[qi * LDB + pj], a11 = A[qi * LDB + qj];
                    float b00 = ci * a00 - si * a10, b01 = ci * a01 - si * a11;
                    float b10 = si * a00 + ci * a10, b11 = si * a01 + ci * a11;
                    A[pi * LDB + pj] = cj * b00 - sj * b01;
                    A[pi * LDB + qj] = sj * b00 + cj * b01;
                    A[qi * LDB + pj] = cj * b10 - sj * b11;
                    A[qi * LDB + qj] = sj * b10 + cj * b11;
                } else {
                    int w = u - 1024;
                    int kk = w >> 4, c4 = (w & 15) << 2;
                    int p = (kk == 0) ? 0 : 1 + (kk - 1 + rr) % 63, q = 1 + (62 - kk + rr) % 63;
                    float c = cbuf[kk], s = sbuf[kk];
                    float4 vp = *(float4*)&VT[p * LDB + c4];
                    float4 vq = *(float4*)&VT[q * LDB + c4];
                    float4 np, nq;
                    np.x = c*vp.x - s*vq.x; np.y = c*vp.y - s*vq.y; np.z = c*vp.z - s*vq.z; np.w = c*vp.w - s*vq.w;
                    nq.x = s*vp.x + c*vq.x; nq.y = s*vp.y + c*vq.y; nq.z = s*vp.z + c*vq.z; nq.w = s*vp.w + c*vq.w;
                    *(float4*)&VT[p * LDB + c4] = np;
                    *(float4*)&VT[q * LDB + c4] = nq;
                }
            }
            __syncthreads();
        }
    }
}

// ---------------- kernel 0: arithmetic mean ----------------
__global__ __launch_bounds__(256) void mean_partial_kernel(const float* __restrict__ x) {
    const int g = blockIdx.x, tid = threadIdx.x;
    float4 acc[4] = {{0,0,0,0},{0,0,0,0},{0,0,0,0},{0,0,0,0}};
    const float4* xb = (const float4*)(x + (size_t)g * K0_NB * NN);
    for (int b = 0; b < K0_NB; ++b) {
#pragma unroll
        for (int i = 0; i < 4; ++i) {
            float4 v = xb[(size_t)b * 1024 + tid + (i << 8)];
            acc[i].x += v.x; acc[i].y += v.y; acc[i].z += v.z; acc[i].w += v.w;
        }
    }
    float4* pm = (float4*)(g_partial_mean + (size_t)g * NN);
#pragma unroll
    for (int i = 0; i < 4; ++i) pm[tid + (i << 8)] = acc[i];
}

__global__ void reduce_mean_kernel() {
    int j = blockIdx.x * 128 + threadIdx.x;
    float acc = 0.f;
    for (int g = 0; g < K0_BLOCKS; ++g) acc += g_partial_mean[(size_t)g * NN + j];
    g_mean[j] = acc * (1.0f / BATCH);
}

// ---------------- kernel 1: eigh(mean)->s,si ; eigh(G)->gsqrt ----------------
__global__ __launch_bounds__(256) void prep_kernel(const float* __restrict__ G) {
    extern __shared__ float sm[];
    float* A    = sm;
    float* Bsc  = A + 4352;
    float* nbuf = Bsc + 4352;
    int* flag   = (int*)(nbuf + 64);
    const int tid = threadIdx.x;
    load_tile(blockIdx.x == 0 ? g_mean : G, A);
    __syncthreads();
    jacobi_onesided(A, nbuf, flag, SWEEPS_SMALL);
    const int j = tid >> 2, seg = tid & 3;
    float4 v[4];
    float n = colnrm2(A, j, seg, v);
    float lam = fmaxf(sqrtf(n), EPSF);
    float inv_n = 1.0f / n;
    scale_store(Bsc, j, seg, v, sqrtf(lam) * inv_n);
    __syncthreads();
    gram_t4(Bsc, A, blockIdx.x == 0 ? g_s : g_gsqrt, 64);
    if (blockIdx.x == 0) {
        __syncthreads();
        scale_store(Bsc, j, seg, v, rsqrtf(lam) * inv_n);
        __syncthreads();
        gram_t4(Bsc, A, g_si, 64);
    }
}

// ---------------- kernel 2: per-batch logm(si x si), partial sums ----------------
__global__ __launch_bounds__(256, 4) void batch_log_kernel(const float* __restrict__ x) {
    extern __shared__ float sm[];
    float* sis  = sm;            // 4352
    float* b1   = sis + 4352;    // 4352
    float* b2   = b1 + 4352;     // 4352
    float* fbuf = b2 + 4352;     // 64
    float* nbuf = fbuf + 64;     // 64
    int* flag   = (int*)(nbuf + 64);
    const int tid = threadIdx.x;
    load_tile(g_si, sis);
    __syncthreads();
    const int r0 = (tid >> 4) << 2, c0 = (tid & 15) << 2;
    const int j = tid >> 2, seg = tid & 3;
    u64 tacc[8];
#pragma unroll
    for (int i = 0; i < 8; ++i) tacc[i] = 0ull;

    for (int m = 0; m < K2_NB; ++m) {
        const float* xb = x + ((size_t)blockIdx.x * K2_NB + m) * NN;
        load_tile(xb, b1);
        __syncthreads();
        mm64_t4(sis, b1, b2, LDB);  __syncthreads();   // P = si @ x
        mm64_t4(b2, sis, b1, LDB);  __syncthreads();   // A = P @ si (symmetric)
        jacobi_onesided(b1, nbuf, flag, SWEEPS_BATCH); // cols b_j = lam_j u_j
        {
            float4 v[4];
            float n = colnrm2(b1, j, seg, v);
            if (seg == 0) {
                float lam = sqrtf(n);
                fbuf[j] = logf(fmaxf(lam, EPSF)) / n;   // log(lam)/lam^2
            }
        }
        __syncthreads();
        {   // tacc += sum_j f_j * b_j b_j^T  (4x4 tile at r0,c0)
#pragma unroll 4
            for (int jj = 0; jj < 64; ++jj) {
                float f = fbuf[jj];
                float4 u = *(const float4*)&b1[jj * LDB + r0];
                ulonglong2 b = *(const ulonglong2*)&b1[jj * LDB + c0];
                u64 p;
                p = pk2(f * u.x, f * u.x); tacc[0] = fma2(p, b.x, tacc[0]); tacc[1] = fma2(p, b.y, tacc[1]);
                p = pk2(f * u.y, f * u.y); tacc[2] = fma2(p, b.x, tacc[2]); tacc[3] = fma2(p, b.y, tacc[3]);
                p = pk2(f * u.z, f * u.z); tacc[4] = fma2(p, b.x, tacc[4]); tacc[5] = fma2(p, b.y, tacc[5]);
                p = pk2(f * u.w, f * u.w); tacc[6] = fma2(p, b.x, tacc[6]); tacc[7] = fma2(p, b.y, tacc[7]);
            }
        }
        __syncthreads();
    }
    float* pt = g_partial_t + (size_t)blockIdx.x * NN;
#pragma unroll
    for (int i = 0; i < 4; ++i)
        *(ulonglong2*)&pt[(r0 + i) * 64 + c0] = make_ulonglong2(tacc[2 * i], tacc[2 * i + 1]);
}

__global__ void reduce_t_kernel() {
    int j = blockIdx.x * 128 + threadIdx.x;
    float acc = 0.f;
    for (int g = 0; g < K2_BLOCKS; ++g) acc += g_partial_t[(size_t)g * NN + j];
    g_tmean[j] = acc * (1.0f / BATCH);
}

// ---------------- kernel 3: expm(tmean), center, csi, W, WT ----------------
__global__ __launch_bounds__(256) void center_kernel() {
    extern __shared__ float sm[];
    float* A  = sm;
    float* VT = A + 4352;
    float* T1 = VT + 4352;
    float* T2 = T1 + 4352;
    float* fw = T2 + 4352;
    float* cb = fw + 64;
    float* sb = cb + 32;
    float* nbuf = sb + 32;
    int* flag = (int*)(nbuf + 64);
    const int tid = threadIdx.x;

    load_tile(g_tmean, A);
    __syncthreads();
    jacobi_twosided(A, VT, cb, sb, SWEEPS_TS);
    if (tid < 64) fw[tid] = expf(A[tid * LDB + tid]);
    __syncthreads();
    for (int idx = tid; idx < NN; idx += 256) {
        int k2 = idx >> 6, i = idx & 63;
        T1[k2 * LDB + i] = fw[k2] * VT[k2 * LDB + i];
    }
    __syncthreads();
    gram_t4(T1, VT, T2, LDB);           // T2 = expm(tmean)
    __syncthreads();
    load_tile(g_s, A);
    __syncthreads();
    mm64_t4(A, T2, T1, LDB);  __syncthreads();  // T1 = s E
    mm64_t4(T1, A, T2, LDB);  __syncthreads();  // T2 = center (SPD)
    jacobi_onesided(T2, nbuf, flag, SWEEPS_SMALL);
    {
        const int j = tid >> 2, seg = tid & 3;
        float4 v[4];
        float n = colnrm2(T2, j, seg, v);
        float lam = fmaxf(sqrtf(n), EPSF);
        float f = rsqrtf(lam) / n;
        scale_store(T1, j, seg, v, f);
    }
    __syncthreads();
    gram_t4(T1, T2, A, LDB);            // A = csi
    __syncthreads();
    load_tile(g_gsqrt, VT);
    __syncthreads();
    mm64_t4(VT, A, T1, LDB);            // T1 = g_sqrt @ csi = W
    __syncthreads();
    store_tile(T1, g_W);
    for (int idx = tid; idx < NN; idx += 256) {
        int rr = idx >> 6, cc = idx & 63;
        g_WT[(cc << 6) + rr] = T1[rr * LDB + cc];
    }
}

// ---------------- kernel 4: out_b = W x_b W^T ----------------
__global__ __launch_bounds__(256) void output_kernel(const float* __restrict__ x,
                                                     float* __restrict__ out) {
    extern __shared__ float sm[];
    float* Ws = sm;
    float* WT = Ws + 4352;
    float* xs = WT + 4352;
    float* P  = xs + 4352;
    load_tile(g_W, Ws);
    load_tile(g_WT, WT);
    load_tile(x + (size_t)blockIdx.x * NN, xs);
    __syncthreads();
    mm64_t4(Ws, xs, P, LDB);            // P = W @ x
    __syncthreads();
    mm64_t4(P, WT, out + (size_t)blockIdx.x * NN, 64);  // out = P @ W^T
}

// ---------------- launcher ----------------
extern "C" void kernel_launch(void* const* d_in, const int* in_sizes, int n_in,
                              void* d_out, int out_size) {
    const float* x;
    const float* G;
    if (in_sizes[0] == NN) { G = (const float*)d_in[0]; x = (const float*)d_in[1]; }
    else                   { x = (const float*)d_in[0]; G = (const float*)d_in[1]; }
    float* out = (float*)d_out;

    constexpr size_t SM_PREP   = (size_t)(2 * 4352 + 64 + 4) * 4;
    constexpr size_t SM_BATCH  = (size_t)(3 * 4352 + 64 + 64 + 4) * 4;
    constexpr size_t SM_CENTER = (size_t)(4 * 4352 + 64 + 32 + 32 + 64 + 4) * 4;
    constexpr size_t SM_OUT    = (size_t)(4 * 4352) * 4;

    cudaFuncSetAttribute(batch_log_kernel, cudaFuncAttributeMaxDynamicSharedMemorySize, (int)SM_BATCH);
    cudaFuncSetAttribute(center_kernel,    cudaFuncAttributeMaxDynamicSharedMemorySize, (int)SM_CENTER);
    cudaFuncSetAttribute(output_kernel,    cudaFuncAttributeMaxDynamicSharedMemorySize, (int)SM_OUT);

    mean_partial_kernel<<<K0_BLOCKS, 256>>>(x);
    reduce_mean_kernel<<<32, 128>>>();
    prep_kernel<<<2, 256, SM_PREP>>>(G);
    batch_log_kernel<<<K2_BLOCKS, 256, SM_BATCH>>>(x);
    reduce_t_kernel<<<32, 128>>>();
    center_kernel<<<1, 256, SM_CENTER>>>();
    output_kernel<<<BATCH, 256, SM_OUT>>>(x, out);
}

// round 9
// speedup vs baseline: 1.0043x; 1.0043x over previous
#include <cuda_runtime.h>
#include <math.h>
#include <stdint.h>

#define BATCH 8192
#define NN 4096
#define LDB 68           // padded stride (floats), float4-aligned
#define EPSF 1e-8f
#define SKIP_TAU 1e-6f

#define K0_BLOCKS 256
#define K0_NB 32
#define K2_BLOCKS 2048
#define K2_NB 4
#define SWEEPS_BATCH 7
#define SWEEPS_SMALL 8
#define SWEEPS_TS 8

// ---------------- device scratch ----------------
__device__ __align__(256) float g_partial_mean[(size_t)K0_BLOCKS * NN];
__device__ __align__(256) float g_mean[NN];
__device__ __align__(256) float g_s[NN];
__device__ __align__(256) float g_si[NN];
__device__ __align__(256) float g_gsqrt[NN];
__device__ __align__(256) float g_W[NN];
__device__ __align__(256) float g_WT[NN];
__device__ __align__(256) float g_partial_t[(size_t)K2_BLOCKS * NN];
__device__ __align__(256) float g_tmean[NN];

// ---------------- packed f32x2 helpers ----------------
typedef unsigned long long u64;
__device__ __forceinline__ u64 pk2(float x, float y) {
    u64 r; asm("mov.b64 %0,{%1,%2};" : "=l"(r) : "f"(x), "f"(y)); return r;
}
__device__ __forceinline__ void up2(u64 v, float& x, float& y) {
    asm("mov.b64 {%0,%1},%2;" : "=f"(x), "=f"(y) : "l"(v));
}
__device__ __forceinline__ u64 fma2(u64 a, u64 b, u64 c) {
    u64 d; asm("fma.rn.f32x2 %0,%1,%2,%3;" : "=l"(d) : "l"(a), "l"(b), "l"(c)); return d;
}
__device__ __forceinline__ u64 mul2(u64 a, u64 b) {
    u64 d; asm("mul.rn.f32x2 %0,%1,%2;" : "=l"(d) : "l"(a), "l"(b)); return d;
}

// ---------------- tile movement (256 threads) ----------------
__device__ __forceinline__ void load_tile(const float* __restrict__ g, float* __restrict__ s) {
    for (int i = threadIdx.x; i < 1024; i += 256) {
        int r = i >> 4, c4 = (i & 15) << 2;
        *(float4*)&s[r * LDB + c4] = *(const float4*)&g[(r << 6) + c4];
    }
}
__device__ __forceinline__ void store_tile(const float* __restrict__ s, float* __restrict__ g) {
    for (int i = threadIdx.x; i < 1024; i += 256) {
        int r = i >> 4, c4 = (i & 15) << 2;
        *(float4*)&g[(r << 6) + c4] = *(const float4*)&s[r * LDB + c4];
    }
}

// ---------------- 4x4 register-tiled matmul: C = A @ B (256 threads) ----------------
__device__ __forceinline__ void mm64_t4(const float* __restrict__ A, const float* __restrict__ B,
                                        float* __restrict__ C, int cstride) {
    const int r0 = (threadIdx.x >> 4) << 2;
    const int c0 = (threadIdx.x & 15) << 2;
    u64 acc[8];
#pragma unroll
    for (int i = 0; i < 8; ++i) acc[i] = 0ull;
#pragma unroll 4
    for (int k = 0; k < 64; ++k) {
        float a0 = A[r0 * LDB + k],       a1 = A[(r0 + 1) * LDB + k];
        float a2 = A[(r0 + 2) * LDB + k], a3 = A[(r0 + 3) * LDB + k];
        ulonglong2 b = *(const ulonglong2*)&B[k * LDB + c0];
        u64 p;
        p = pk2(a0, a0); acc[0] = fma2(p, b.x, acc[0]); acc[1] = fma2(p, b.y, acc[1]);
        p = pk2(a1, a1); acc[2] = fma2(p, b.x, acc[2]); acc[3] = fma2(p, b.y, acc[3]);
        p = pk2(a2, a2); acc[4] = fma2(p, b.x, acc[4]); acc[5] = fma2(p, b.y, acc[5]);
        p = pk2(a3, a3); acc[6] = fma2(p, b.x, acc[6]); acc[7] = fma2(p, b.y, acc[7]);
    }
#pragma unroll
    for (int i = 0; i < 4; ++i)
        *(ulonglong2*)&C[(r0 + i) * cstride + c0] = make_ulonglong2(acc[2 * i], acc[2 * i + 1]);
}

// out[r][c] = sum_j Bs[j][r] * B[j][c], 4x4 tiles.
__device__ __forceinline__ void gram_t4(const float* __restrict__ Bs, const float* __restrict__ B,
                                        float* __restrict__ out, int ostride) {
    const int r0 = (threadIdx.x >> 4) << 2;
    const int c0 = (threadIdx.x & 15) << 2;
    u64 acc[8];
#pragma unroll
    for (int i = 0; i < 8; ++i) acc[i] = 0ull;
#pragma unroll 4
    for (int j = 0; j < 64; ++j) {
        float4 u = *(const float4*)&Bs[j * LDB + r0];
        ulonglong2 b = *(const ulonglong2*)&B[j * LDB + c0];
        u64 p;
        p = pk2(u.x, u.x); acc[0] = fma2(p, b.x, acc[0]); acc[1] = fma2(p, b.y, acc[1]);
        p = pk2(u.y, u.y); acc[2] = fma2(p, b.x, acc[2]); acc[3] = fma2(p, b.y, acc[3]);
        p = pk2(u.z, u.z); acc[4] = fma2(p, b.x, acc[4]); acc[5] = fma2(p, b.y, acc[5]);
        p = pk2(u.w, u.w); acc[6] = fma2(p, b.x, acc[6]); acc[7] = fma2(p, b.y, acc[7]);
    }
#pragma unroll
    for (int i = 0; i < 4; ++i)
        *(ulonglong2*)&out[(r0 + i) * ostride + c0] = make_ulonglong2(acc[2 * i], acc[2 * i + 1]);
}

__device__ __forceinline__ float colnrm2(const float* __restrict__ B, int j, int seg, float4 v[4]) {
    const float4* c = (const float4*)(B + j * LDB + (seg << 4));
    v[0] = c[0]; v[1] = c[1]; v[2] = c[2]; v[3] = c[3];
    float n = v[0].x * v[0].x;
    n = fmaf(v[0].y, v[0].y, n); n = fmaf(v[0].z, v[0].z, n); n = fmaf(v[0].w, v[0].w, n);
    n = fmaf(v[1].x, v[1].x, n); n = fmaf(v[1].y, v[1].y, n); n = fmaf(v[1].z, v[1].z, n); n = fmaf(v[1].w, v[1].w, n);
    n = fmaf(v[2].x, v[2].x, n); n = fmaf(v[2].y, v[2].y, n); n = fmaf(v[2].z, v[2].z, n); n = fmaf(v[2].w, v[2].w, n);
    n = fmaf(v[3].x, v[3].x, n); n = fmaf(v[3].y, v[3].y, n); n = fmaf(v[3].z, v[3].z, n); n = fmaf(v[3].w, v[3].w, n);
    n += __shfl_xor_sync(0xffffffffu, n, 1);
    n += __shfl_xor_sync(0xffffffffu, n, 2);
    return n;
}

__device__ __forceinline__ void scale_store(float* __restrict__ D, int j, int seg,
                                            const float4 v[4], float f) {
    float4* d = (float4*)(D + j * LDB + (seg << 4));
    d[0] = make_float4(f * v[0].x, f * v[0].y, f * v[0].z, f * v[0].w);
    d[1] = make_float4(f * v[1].x, f * v[1].y, f * v[1].z, f * v[1].w);
    d[2] = make_float4(f * v[2].x, f * v[2].y, f * v[2].z, f * v[2].w);
    d[3] = make_float4(f * v[3].x, f * v[3].y, f * v[3].z, f * v[3].w);
}

// ---------------- single-matrix one-sided Jacobi (side kernels) ----------------
__device__ void jacobi_onesided(float* __restrict__ B, float* __restrict__ nbuf, int sweeps) {
    const int tid = threadIdx.x;
    const int k = tid >> 3;
    const int o0 = (tid & 7) << 2;
    const int o1 = 32 + o0;
    const int jn = tid >> 2, segn = tid & 3;
    for (int sw = 0; sw < sweeps; ++sw) {
        {
            float4 v[4];
            float n = colnrm2(B, jn, segn, v);
            if (segn == 0) nbuf[jn] = n;
        }
        __syncthreads();
        int p = (k == 0) ? 0 : k;
        int q = 63 - k;
        for (int rr = 0; rr < 63; ++rr) {
            float* bp = B + p * LDB;
            float* bq = B + q * LDB;
            ulonglong2 P0 = *(ulonglong2*)(bp + o0), P1 = *(ulonglong2*)(bp + o1);
            ulonglong2 Q0 = *(ulonglong2*)(bq + o0), Q1 = *(ulonglong2*)(bq + o1);
            u64 spq = mul2(P0.x, Q0.x);
            spq = fma2(P0.y, Q0.y, spq); spq = fma2(P1.x, Q1.x, spq); spq = fma2(P1.y, Q1.y, spq);
            float a0, a1;
            up2(spq, a0, a1);
            float apq = a0 + a1;
            apq += __shfl_xor_sync(0xffffffffu, apq, 1);
            apq += __shfl_xor_sync(0xffffffffu, apq, 2);
            apq += __shfl_xor_sync(0xffffffffu, apq, 4);
            float app = nbuf[p], aqq = nbuf[q];
            if (apq * apq > SKIP_TAU * SKIP_TAU * app * aqq) {
                float zeta = (aqq - app) / (2.0f * apq);
                float t = copysignf(1.0f, zeta) / (fabsf(zeta) + sqrtf(fmaf(zeta, zeta, 1.0f)));
                float c = rsqrtf(fmaf(t, t, 1.0f));
                float s = t * c;
                u64 c2 = pk2(c, c), s2 = pk2(s, s), ns2 = pk2(-s, -s);
                ulonglong2 NP0, NP1, NQ0, NQ1;
                NP0.x = fma2(c2, P0.x, mul2(ns2, Q0.x));
                NP0.y = fma2(c2, P0.y, mul2(ns2, Q0.y));
                NP1.x = fma2(c2, P1.x, mul2(ns2, Q1.x));
                NP1.y = fma2(c2, P1.y, mul2(ns2, Q1.y));
                NQ0.x = fma2(s2, P0.x, mul2(c2, Q0.x));
                NQ0.y = fma2(s2, P0.y, mul2(c2, Q0.y));
                NQ1.x = fma2(s2, P1.x, mul2(c2, Q1.x));
                NQ1.y = fma2(s2, P1.y, mul2(c2, Q1.y));
                *(ulonglong2*)(bp + o0) = NP0; *(ulonglong2*)(bp + o1) = NP1;
                *(ulonglong2*)(bq + o0) = NQ0; *(ulonglong2*)(bq + o1) = NQ1;
                if ((tid & 7) == 0) {
                    float d = t * apq;
                    nbuf[p] = app - d;
                    nbuf[q] = aqq + d;
                }
            }
            if (k) p = (p == 63) ? 1 : p + 1;
            q = (q == 63) ? 1 : q + 1;
            __syncthreads();
        }
    }
}

// ---------------- DUAL-matrix one-sided Jacobi: 2x work per barrier ----------------
// Same octet/pair mapping as jacobi_onesided, applied to matrices BA and BB in
// the same round: one __syncthreads() covers both rotations (2x ILP per thread,
// half the barriers per matrix).
__device__ void jacobi2(float* __restrict__ BA, float* __restrict__ BB,
                        float* __restrict__ nbA, float* __restrict__ nbB, int sweeps) {
    const int tid = threadIdx.x;
    const int k = tid >> 3;
    const int o0 = (tid & 7) << 2;
    const int o1 = 32 + o0;
    const int jn = tid >> 2, segn = tid & 3;
    for (int sw = 0; sw < sweeps; ++sw) {
        {
            float4 v[4];
            float nA = colnrm2(BA, jn, segn, v);
            float nB = colnrm2(BB, jn, segn, v);
            if (segn == 0) { nbA[jn] = nA; nbB[jn] = nB; }
        }
        __syncthreads();
        int p = (k == 0) ? 0 : k;
        int q = 63 - k;
        for (int rr = 0; rr < 63; ++rr) {
            float* bpA = BA + p * LDB; float* bqA = BA + q * LDB;
            float* bpB = BB + p * LDB; float* bqB = BB + q * LDB;
            ulonglong2 PA0 = *(ulonglong2*)(bpA + o0), PA1 = *(ulonglong2*)(bpA + o1);
            ulonglong2 QA0 = *(ulonglong2*)(bqA + o0), QA1 = *(ulonglong2*)(bqA + o1);
            ulonglong2 PB0 = *(ulonglong2*)(bpB + o0), PB1 = *(ulonglong2*)(bpB + o1);
            ulonglong2 QB0 = *(ulonglong2*)(bqB + o0), QB1 = *(ulonglong2*)(bqB + o1);
            u64 dA = mul2(PA0.x, QA0.x);
            u64 dB = mul2(PB0.x, QB0.x);
            dA = fma2(PA0.y, QA0.y, dA); dB = fma2(PB0.y, QB0.y, dB);
            dA = fma2(PA1.x, QA1.x, dA); dB = fma2(PB1.x, QB1.x, dB);
            dA = fma2(PA1.y, QA1.y, dA); dB = fma2(PB1.y, QB1.y, dB);
            float a0, a1;
            up2(dA, a0, a1); float apqA = a0 + a1;
            up2(dB, a0, a1); float apqB = a0 + a1;
            apqA += __shfl_xor_sync(0xffffffffu, apqA, 1);
            apqB += __shfl_xor_sync(0xffffffffu, apqB, 1);
            apqA += __shfl_xor_sync(0xffffffffu, apqA, 2);
            apqB += __shfl_xor_sync(0xffffffffu, apqB, 2);
            apqA += __shfl_xor_sync(0xffffffffu, apqA, 4);
            apqB += __shfl_xor_sync(0xffffffffu, apqB, 4);
            float appA = nbA[p], aqqA = nbA[q];
            float appB = nbB[p], aqqB = nbB[q];
            bool rotA = apqA * apqA > SKIP_TAU * SKIP_TAU * appA * aqqA;
            bool rotB = apqB * apqB > SKIP_TAU * SKIP_TAU * appB * aqqB;
            float tA = 0.f, tB = 0.f;
            if (rotA) {
                float z = (aqqA - appA) / (2.0f * apqA);
                tA = copysignf(1.0f, z) / (fabsf(z) + sqrtf(fmaf(z, z, 1.0f)));
                float c = rsqrtf(fmaf(tA, tA, 1.0f));
                float s = tA * c;
                u64 c2 = pk2(c, c), s2 = pk2(s, s), ns2 = pk2(-s, -s);
                ulonglong2 NP0, NP1, NQ0, NQ1;
                NP0.x = fma2(c2, PA0.x, mul2(ns2, QA0.x));
                NP0.y = fma2(c2, PA0.y, mul2(ns2, QA0.y));
                NP1.x = fma2(c2, PA1.x, mul2(ns2, QA1.x));
                NP1.y = fma2(c2, PA1.y, mul2(ns2, QA1.y));
                NQ0.x = fma2(s2, PA0.x, mul2(c2, QA0.x));
                NQ0.y = fma2(s2, PA0.y, mul2(c2, QA0.y));
                NQ1.x = fma2(s2, PA1.x, mul2(c2, QA1.x));
                NQ1.y = fma2(s2, PA1.y, mul2(c2, QA1.y));
                *(ulonglong2*)(bpA + o0) = NP0; *(ulonglong2*)(bpA + o1) = NP1;
                *(ulonglong2*)(bqA + o0) = NQ0; *(ulonglong2*)(bqA + o1) = NQ1;
            }
            if (rotB) {
                float z = (aqqB - appB) / (2.0f * apqB);
                tB = copysignf(1.0f, z) / (fabsf(z) + sqrtf(fmaf(z, z, 1.0f)));
                float c = rsqrtf(fmaf(tB, tB, 1.0f));
                float s = tB * c;
                u64 c2 = pk2(c, c), s2 = pk2(s, s), ns2 = pk2(-s, -s);
                ulonglong2 NP0, NP1, NQ0, NQ1;
                NP0.x = fma2(c2, PB0.x, mul2(ns2, QB0.x));
                NP0.y = fma2(c2, PB0.y, mul2(ns2, QB0.y));
                NP1.x = fma2(c2, PB1.x, mul2(ns2, QB1.x));
                NP1.y = fma2(c2, PB1.y, mul2(ns2, QB1.y));
                NQ0.x = fma2(s2, PB0.x, mul2(c2, QB0.x));
                NQ0.y = fma2(s2, PB0.y, mul2(c2, QB0.y));
                NQ1.x = fma2(s2, PB1.x, mul2(c2, QB1.x));
                NQ1.y = fma2(s2, PB1.y, mul2(c2, QB1.y));
                *(ulonglong2*)(bpB + o0) = NP0; *(ulonglong2*)(bpB + o1) = NP1;
                *(ulonglong2*)(bqB + o0) = NQ0; *(ulonglong2*)(bqB + o1) = NQ1;
            }
            if ((tid & 7) == 0) {
                if (rotA) {
                    float d = tA * apqA;
                    nbA[p] = appA - d; nbA[q] = aqqA + d;
                }
                if (rotB) {
                    float d = tB * apqB;
                    nbB[p] = appB - d; nbB[q] = aqqB + d;
                }
            }
            if (k) p = (p == 63) ? 1 : p + 1;
            q = (q == 63) ? 1 : q + 1;
            __syncthreads();
        }
    }
}

// ---------------- two-sided Jacobi (only for indefinite tmean) ----------------
__device__ void jacobi_twosided(float* __restrict__ A, float* __restrict__ VT,
                                float* cbuf, float* sbuf, int sweeps) {
    const int tid = threadIdx.x;
    for (int idx = tid; idx < NN; idx += 256) {
        int r = idx >> 6, c = idx & 63;
        VT[r * LDB + c] = (r == c) ? 1.f : 0.f;
    }
    __syncthreads();
    for (int sw = 0; sw < sweeps; ++sw) {
        for (int rr = 0; rr < 63; ++rr) {
            if (tid < 32) {
                int p = (tid == 0) ? 0 : 1 + (tid - 1 + rr) % 63;
                int q = 1 + (62 - tid + rr) % 63;
                float app = A[p * LDB + p], aqq = A[q * LDB + q], apq = A[p * LDB + q];
                float c, s;
                if (fabsf(apq) > 1e-30f) {
                    float th = 0.5f * (aqq - app) / apq;
                    float t = copysignf(1.f, th) / (fabsf(th) + sqrtf(fmaf(th, th, 1.f)));
                    c = rsqrtf(fmaf(t, t, 1.f)); s = t * c;
                } else { c = 1.f; s = 0.f; }
                cbuf[tid] = c; sbuf[tid] = s;
            }
            __syncthreads();
            for (int u = tid; u < 1536; u += 256) {
                if (u < 1024) {
                    int ki = u & 31, kj = u >> 5;
                    int pi = (ki == 0) ? 0 : 1 + (ki - 1 + rr) % 63, qi = 1 + (62 - ki + rr) % 63;
                    int pj = (kj == 0) ? 0 : 1 + (kj - 1 + rr) % 63, qj = 1 + (62 - kj + rr) % 63;
                    float ci = cbuf[ki], si = sbuf[ki], cj = cbuf[kj], sj = sbuf[kj];
                    float a00 = A[pi * LDB + pj], a01 = A[pi * LDB + qj];
                    float a10 = A[qi * LDB + pj], a11 = A[qi * LDB + qj];
                    float b00 = ci * a00 - si * a10, b01 = ci * a01 - si * a11;
                    float b10 = si * a00 + ci * a10, b11 = si * a01 + ci * a11;
                    A[pi * LDB + pj] = cj * b00 - sj * b01;
                    A[pi * LDB + qj] = sj * b00 + cj * b01;
                    A[qi * LDB + pj] = cj * b10 - sj * b11;
                    A[qi * LDB + qj] = sj * b10 + cj * b11;
                } else {
                    int w = u - 1024;
                    int kk = w >> 4, c4 = (w & 15) << 2;
                    int p = (kk == 0) ? 0 : 1 + (kk - 1 + rr) % 63, q = 1 + (62 - kk + rr) % 63;
                    float c = cbuf[kk], s = sbuf[kk];
                    float4 vp = *(float4*)&VT[p * LDB + c4];
                    float4 vq = *(float4*)&VT[q * LDB + c4];
                    float4 np, nq;
                    np.x = c*vp.x - s*vq.x; np.y = c*vp.y - s*vq.y; np.z = c*vp.z - s*vq.z; np.w = c*vp.w - s*vq.w;
                    nq.x = s*vp.x + c*vq.x; nq.y = s*vp.y + c*vq.y; nq.z = s*vp.z + c*vq.z; nq.w = s*vp.w + c*vq.w;
                    *(float4*)&VT[p * LDB + c4] = np;
                    *(float4*)&VT[q * LDB + c4] = nq;
                }
            }
            __syncthreads();
        }
    }
}

// ---------------- kernel 0: arithmetic mean ----------------
__global__ __launch_bounds__(256) void mean_partial_kernel(const float* __restrict__ x) {
    const int g = blockIdx.x, tid = threadIdx.x;
    float4 acc[4] = {{0,0,0,0},{0,0,0,0},{0,0,0,0},{0,0,0,0}};
    const float4* xb = (const float4*)(x + (size_t)g * K0_NB * NN);
    for (int b = 0; b < K0_NB; ++b) {
#pragma unroll
        for (int i = 0; i < 4; ++i) {
            float4 v = xb[(size_t)b * 1024 + tid + (i << 8)];
            acc[i].x += v.x; acc[i].y += v.y; acc[i].z += v.z; acc[i].w += v.w;
        }
    }
    float4* pm = (float4*)(g_partial_mean + (size_t)g * NN);
#pragma unroll
    for (int i = 0; i < 4; ++i) pm[tid + (i << 8)] = acc[i];
}

__global__ void reduce_mean_kernel() {
    int j = blockIdx.x * 128 + threadIdx.x;
    float acc = 0.f;
    for (int g = 0; g < K0_BLOCKS; ++g) acc += g_partial_mean[(size_t)g * NN + j];
    g_mean[j] = acc * (1.0f / BATCH);
}

// ---------------- kernel 1: eigh(mean)->s,si ; eigh(G)->gsqrt ----------------
__global__ __launch_bounds__(256) void prep_kernel(const float* __restrict__ G) {
    extern __shared__ float sm[];
    float* A    = sm;
    float* Bsc  = A + 4352;
    float* nbuf = Bsc + 4352;
    const int tid = threadIdx.x;
    load_tile(blockIdx.x == 0 ? g_mean : G, A);
    __syncthreads();
    jacobi_onesided(A, nbuf, SWEEPS_SMALL);
    const int j = tid >> 2, seg = tid & 3;
    float4 v[4];
    float n = colnrm2(A, j, seg, v);
    float lam = fmaxf(sqrtf(n), EPSF);
    float inv_n = 1.0f / n;
    scale_store(Bsc, j, seg, v, sqrtf(lam) * inv_n);
    __syncthreads();
    gram_t4(Bsc, A, blockIdx.x == 0 ? g_s : g_gsqrt, 64);
    if (blockIdx.x == 0) {
        __syncthreads();
        scale_store(Bsc, j, seg, v, rsqrtf(lam) * inv_n);
        __syncthreads();
        gram_t4(Bsc, A, g_si, 64);
    }
}

// ---------------- kernel 2: per-batch logm(si x si), dual-matrix Jacobi ----------------
__global__ __launch_bounds__(256, 3) void batch_log_kernel(const float* __restrict__ x) {
    extern __shared__ float sm[];
    float* T0 = sm;              // sis (persistent)
    float* T1 = T0 + 4352;       // matrix A
    float* T2 = T1 + 4352;       // matrix B
    float* T3 = T2 + 4352;       // scratch
    float* nbA = T3 + 4352;      // 64 (norms A -> log factors A)
    float* nbB = nbA + 64;       // 64
    const int tid = threadIdx.x;
    load_tile(g_si, T0);
    __syncthreads();
    const int r0 = (tid >> 4) << 2, c0 = (tid & 15) << 2;
    const int j = tid >> 2, seg = tid & 3;
    u64 tacc[8];
#pragma unroll
    for (int i = 0; i < 8; ++i) tacc[i] = 0ull;

    for (int m = 0; m < K2_NB; m += 2) {
        const float* xbA = x + ((size_t)blockIdx.x * K2_NB + m) * NN;
        const float* xbB = xbA + NN;
        load_tile(xbA, T2);
        __syncthreads();
        mm64_t4(T0, T2, T3, LDB);  __syncthreads();   // P = si @ xA
        mm64_t4(T3, T0, T1, LDB);  __syncthreads();   // A-matrix -> T1
        load_tile(xbB, T3);
        __syncthreads();
        mm64_t4(T0, T3, T2, LDB);  __syncthreads();   // P = si @ xB (T2 scratch)
        mm64_t4(T2, T0, T3, LDB);  __syncthreads();   // B-matrix -> T3... swap
        // Note: B-matrix ended in T3; run dual Jacobi on (T1, T3).
        jacobi2(T1, T3, nbA, nbB, SWEEPS_BATCH);
        // log factors for both matrices
        {
            float4 v[4];
            float nA = colnrm2(T1, j, seg, v);
            float nB = colnrm2(T3, j, seg, v);
            if (seg == 0) {
                nbA[j] = logf(fmaxf(sqrtf(nA), EPSF)) / nA;
                nbB[j] = logf(fmaxf(sqrtf(nB), EPSF)) / nB;
            }
        }
        __syncthreads();
        // tacc += sum_j fA_j bA_j bA_j^T + fB_j bB_j bB_j^T
#pragma unroll 4
        for (int jj = 0; jj < 64; ++jj) {
            float f = nbA[jj];
            float4 u = *(const float4*)&T1[jj * LDB + r0];
            ulonglong2 b = *(const ulonglong2*)&T1[jj * LDB + c0];
            u64 p;
            p = pk2(f * u.x, f * u.x); tacc[0] = fma2(p, b.x, tacc[0]); tacc[1] = fma2(p, b.y, tacc[1]);
            p = pk2(f * u.y, f * u.y); tacc[2] = fma2(p, b.x, tacc[2]); tacc[3] = fma2(p, b.y, tacc[3]);
            p = pk2(f * u.z, f * u.z); tacc[4] = fma2(p, b.x, tacc[4]); tacc[5] = fma2(p, b.y, tacc[5]);
            p = pk2(f * u.w, f * u.w); tacc[6] = fma2(p, b.x, tacc[6]); tacc[7] = fma2(p, b.y, tacc[7]);
        }
#pragma unroll 4
        for (int jj = 0; jj < 64; ++jj) {
            float f = nbB[jj];
            float4 u = *(const float4*)&T3[jj * LDB + r0];
            ulonglong2 b = *(const ulonglong2*)&T3[jj * LDB + c0];
            u64 p;
            p = pk2(f * u.x, f * u.x); tacc[0] = fma2(p, b.x, tacc[0]); tacc[1] = fma2(p, b.y, tacc[1]);
            p = pk2(f * u.y, f * u.y); tacc[2] = fma2(p, b.x, tacc[2]); tacc[3] = fma2(p, b.y, tacc[3]);
            p = pk2(f * u.z, f * u.z); tacc[4] = fma2(p, b.x, tacc[4]); tacc[5] = fma2(p, b.y, tacc[5]);
            p = pk2(f * u.w, f * u.w); tacc[6] = fma2(p, b.x, tacc[6]); tacc[7] = fma2(p, b.y, tacc[7]);
        }
        __syncthreads();
    }
    float* pt = g_partial_t + (size_t)blockIdx.x * NN;
#pragma unroll
    for (int i = 0; i < 4; ++i)
        *(ulonglong2*)&pt[(r0 + i) * 64 + c0] = make_ulonglong2(tacc[2 * i], tacc[2 * i + 1]);
}

__global__ void reduce_t_kernel() {
    int j = blockIdx.x * 128 + threadIdx.x;
    float acc = 0.f;
    for (int g = 0; g < K2_BLOCKS; ++g) acc += g_partial_t[(size_t)g * NN + j];
    g_tmean[j] = acc * (1.0f / BATCH);
}

// ---------------- kernel 3: expm(tmean), center, csi, W, WT ----------------
__global__ __launch_bounds__(256) void center_kernel() {
    extern __shared__ float sm[];
    float* A  = sm;
    float* VT = A + 4352;
    float* T1 = VT + 4352;
    float* T2 = T1 + 4352;
    float* fw = T2 + 4352;
    float* cb = fw + 64;
    float* sb = cb + 32;
    float* nbuf = sb + 32;
    const int tid = threadIdx.x;

    load_tile(g_tmean, A);
    __syncthreads();
    jacobi_twosided(A, VT, cb, sb, SWEEPS_TS);
    if (tid < 64) fw[tid] = expf(A[tid * LDB + tid]);
    __syncthreads();
    for (int idx = tid; idx < NN; idx += 256) {
        int k2 = idx >> 6, i = idx & 63;
        T1[k2 * LDB + i] = fw[k2] * VT[k2 * LDB + i];
    }
    __syncthreads();
    gram_t4(T1, VT, T2, LDB);           // T2 = expm(tmean)
    __syncthreads();
    load_tile(g_s, A);
    __syncthreads();
    mm64_t4(A, T2, T1, LDB);  __syncthreads();  // T1 = s E
    mm64_t4(T1, A, T2, LDB);  __syncthreads();  // T2 = center (SPD)
    jacobi_onesided(T2, nbuf, SWEEPS_SMALL);
    {
        const int j = tid >> 2, seg = tid & 3;
        float4 v[4];
        float n = colnrm2(T2, j, seg, v);
        float lam = fmaxf(sqrtf(n), EPSF);
        float f = rsqrtf(lam) / n;
        scale_store(T1, j, seg, v, f);
    }
    __syncthreads();
    gram_t4(T1, T2, A, LDB);            // A = csi
    __syncthreads();
    load_tile(g_gsqrt, VT);
    __syncthreads();
    mm64_t4(VT, A, T1, LDB);            // T1 = g_sqrt @ csi = W
    __syncthreads();
    store_tile(T1, g_W);
    for (int idx = tid; idx < NN; idx += 256) {
        int rr = idx >> 6, cc = idx & 63;
        g_WT[(cc << 6) + rr] = T1[rr * LDB + cc];
    }
}

// ---------------- kernel 4: out_b = W x_b W^T ----------------
__global__ __launch_bounds__(256) void output_kernel(const float* __restrict__ x,
                                                     float* __restrict__ out) {
    extern __shared__ float sm[];
    float* Ws = sm;
    float* WT = Ws + 4352;
    float* xs = WT + 4352;
    float* P  = xs + 4352;
    load_tile(g_W, Ws);
    load_tile(g_WT, WT);
    load_tile(x + (size_t)blockIdx.x * NN, xs);
    __syncthreads();
    mm64_t4(Ws, xs, P, LDB);            // P = W @ x
    __syncthreads();
    mm64_t4(P, WT, out + (size_t)blockIdx.x * NN, 64);  // out = P @ W^T
}

// ---------------- launcher ----------------
extern "C" void kernel_launch(void* const* d_in, const int* in_sizes, int n_in,
                              void* d_out, int out_size) {
    const float* x;
    const float* G;
    if (in_sizes[0] == NN) { G = (const float*)d_in[0]; x = (const float*)d_in[1]; }
    else                   { x = (const float*)d_in[0]; G = (const float*)d_in[1]; }
    float* out = (float*)d_out;

    constexpr size_t SM_PREP   = (size_t)(2 * 4352 + 64) * 4;
    constexpr size_t SM_BATCH  = (size_t)(4 * 4352 + 128) * 4;
    constexpr size_t SM_CENTER = (size_t)(4 * 4352 + 64 + 32 + 32 + 64) * 4;
    constexpr size_t SM_OUT    = (size_t)(4 * 4352) * 4;

    cudaFuncSetAttribute(batch_log_kernel, cudaFuncAttributeMaxDynamicSharedMemorySize, (int)SM_BATCH);
    cudaFuncSetAttribute(center_kernel,    cudaFuncAttributeMaxDynamicSharedMemorySize, (int)SM_CENTER);
    cudaFuncSetAttribute(output_kernel,    cudaFuncAttributeMaxDynamicSharedMemorySize, (int)SM_OUT);

    mean_partial_kernel<<<K0_BLOCKS, 256>>>(x);
    reduce_mean_kernel<<<32, 128>>>();
    prep_kernel<<<2, 256, SM_PREP>>>(G);
    batch_log_kernel<<<K2_BLOCKS, 256, SM_BATCH>>>(x);
    reduce_t_kernel<<<32, 128>>>();
    center_kernel<<<1, 256, SM_CENTER>>>();
    output_kernel<<<BATCH, 256, SM_OUT>>>(x, out);
}

// round 10
// speedup vs baseline: 1.0740x; 1.0694x over previous
#include <cuda_runtime.h>
#include <math.h>
#include <stdint.h>

#define BATCH 8192
#define NN 4096
#define LDB 68           // padded stride (floats), float4-aligned
#define EPSF 1e-8f
#define SKIP_TAU 1e-6f

#define K0_BLOCKS 256
#define K0_NB 32
#define K2_BLOCKS 2048
#define K2_NB 4
#define SWEEPS_BATCH 7
#define SWEEPS_SMALL 8
#define SWEEPS_TS 8

// ---------------- device scratch ----------------
__device__ __align__(256) float g_partial_mean[(size_t)K0_BLOCKS * NN];
__device__ __align__(256) float g_mean[NN];
__device__ __align__(256) float g_s[NN];
__device__ __align__(256) float g_si[NN];
__device__ __align__(256) float g_gsqrt[NN];
__device__ __align__(256) float g_W[NN];
__device__ __align__(256) float g_WT[NN];
__device__ __align__(256) float g_partial_t[(size_t)K2_BLOCKS * NN];
__device__ __align__(256) float g_tmean[NN];

// ---------------- packed f32x2 helpers ----------------
typedef unsigned long long u64;
__device__ __forceinline__ u64 pk2(float x, float y) {
    u64 r; asm("mov.b64 %0,{%1,%2};" : "=l"(r) : "f"(x), "f"(y)); return r;
}
__device__ __forceinline__ void up2(u64 v, float& x, float& y) {
    asm("mov.b64 {%0,%1},%2;" : "=f"(x), "=f"(y) : "l"(v));
}
__device__ __forceinline__ u64 fma2(u64 a, u64 b, u64 c) {
    u64 d; asm("fma.rn.f32x2 %0,%1,%2,%3;" : "=l"(d) : "l"(a), "l"(b), "l"(c)); return d;
}
__device__ __forceinline__ u64 mul2(u64 a, u64 b) {
    u64 d; asm("mul.rn.f32x2 %0,%1,%2;" : "=l"(d) : "l"(a), "l"(b)); return d;
}

// ---------------- tile movement (256 threads) ----------------
__device__ __forceinline__ void load_tile(const float* __restrict__ g, float* __restrict__ s) {
    for (int i = threadIdx.x; i < 1024; i += 256) {
        int r = i >> 4, c4 = (i & 15) << 2;
        *(float4*)&s[r * LDB + c4] = *(const float4*)&g[(r << 6) + c4];
    }
}
__device__ __forceinline__ void store_tile(const float* __restrict__ s, float* __restrict__ g) {
    for (int i = threadIdx.x; i < 1024; i += 256) {
        int r = i >> 4, c4 = (i & 15) << 2;
        *(float4*)&g[(r << 6) + c4] = *(const float4*)&s[r * LDB + c4];
    }
}

// ---------------- 4x4 register-tiled matmul: C = A @ B (256 threads) ----------------
__device__ __forceinline__ void mm64_t4(const float* __restrict__ A, const float* __restrict__ B,
                                        float* __restrict__ C, int cstride) {
    const int r0 = (threadIdx.x >> 4) << 2;
    const int c0 = (threadIdx.x & 15) << 2;
    u64 acc[8];
#pragma unroll
    for (int i = 0; i < 8; ++i) acc[i] = 0ull;
#pragma unroll 4
    for (int k = 0; k < 64; ++k) {
        float a0 = A[r0 * LDB + k],       a1 = A[(r0 + 1) * LDB + k];
        float a2 = A[(r0 + 2) * LDB + k], a3 = A[(r0 + 3) * LDB + k];
        ulonglong2 b = *(const ulonglong2*)&B[k * LDB + c0];
        u64 p;
        p = pk2(a0, a0); acc[0] = fma2(p, b.x, acc[0]); acc[1] = fma2(p, b.y, acc[1]);
        p = pk2(a1, a1); acc[2] = fma2(p, b.x, acc[2]); acc[3] = fma2(p, b.y, acc[3]);
        p = pk2(a2, a2); acc[4] = fma2(p, b.x, acc[4]); acc[5] = fma2(p, b.y, acc[5]);
        p = pk2(a3, a3); acc[6] = fma2(p, b.x, acc[6]); acc[7] = fma2(p, b.y, acc[7]);
    }
#pragma unroll
    for (int i = 0; i < 4; ++i)
        *(ulonglong2*)&C[(r0 + i) * cstride + c0] = make_ulonglong2(acc[2 * i], acc[2 * i + 1]);
}

// In-place: C = A @ B stored OVER B (register staging + internal barrier).
// Caller must sync before; this ends with the store visible only after the
// caller's following __syncthreads().
__device__ __forceinline__ void mm64_t4_ip(const float* __restrict__ A, float* __restrict__ B) {
    const int r0 = (threadIdx.x >> 4) << 2;
    const int c0 = (threadIdx.x & 15) << 2;
    u64 acc[8];
#pragma unroll
    for (int i = 0; i < 8; ++i) acc[i] = 0ull;
#pragma unroll 4
    for (int k = 0; k < 64; ++k) {
        float a0 = A[r0 * LDB + k],       a1 = A[(r0 + 1) * LDB + k];
        float a2 = A[(r0 + 2) * LDB + k], a3 = A[(r0 + 3) * LDB + k];
        ulonglong2 b = *(const ulonglong2*)&B[k * LDB + c0];
        u64 p;
        p = pk2(a0, a0); acc[0] = fma2(p, b.x, acc[0]); acc[1] = fma2(p, b.y, acc[1]);
        p = pk2(a1, a1); acc[2] = fma2(p, b.x, acc[2]); acc[3] = fma2(p, b.y, acc[3]);
        p = pk2(a2, a2); acc[4] = fma2(p, b.x, acc[4]); acc[5] = fma2(p, b.y, acc[5]);
        p = pk2(a3, a3); acc[6] = fma2(p, b.x, acc[6]); acc[7] = fma2(p, b.y, acc[7]);
    }
    __syncthreads();   // all reads of B complete before overwrite
#pragma unroll
    for (int i = 0; i < 4; ++i)
        *(ulonglong2*)&B[(r0 + i) * LDB + c0] = make_ulonglong2(acc[2 * i], acc[2 * i + 1]);
}

// out[r][c] = sum_j Bs[j][r] * B[j][c], 4x4 tiles.
__device__ __forceinline__ void gram_t4(const float* __restrict__ Bs, const float* __restrict__ B,
                                        float* __restrict__ out, int ostride) {
    const int r0 = (threadIdx.x >> 4) << 2;
    const int c0 = (threadIdx.x & 15) << 2;
    u64 acc[8];
#pragma unroll
    for (int i = 0; i < 8; ++i) acc[i] = 0ull;
#pragma unroll 4
    for (int j = 0; j < 64; ++j) {
        float4 u = *(const float4*)&Bs[j * LDB + r0];
        ulonglong2 b = *(const ulonglong2*)&B[j * LDB + c0];
        u64 p;
        p = pk2(u.x, u.x); acc[0] = fma2(p, b.x, acc[0]); acc[1] = fma2(p, b.y, acc[1]);
        p = pk2(u.y, u.y); acc[2] = fma2(p, b.x, acc[2]); acc[3] = fma2(p, b.y, acc[3]);
        p = pk2(u.z, u.z); acc[4] = fma2(p, b.x, acc[4]); acc[5] = fma2(p, b.y, acc[5]);
        p = pk2(u.w, u.w); acc[6] = fma2(p, b.x, acc[6]); acc[7] = fma2(p, b.y, acc[7]);
    }
#pragma unroll
    for (int i = 0; i < 4; ++i)
        *(ulonglong2*)&out[(r0 + i) * ostride + c0] = make_ulonglong2(acc[2 * i], acc[2 * i + 1]);
}

__device__ __forceinline__ float colnrm2(const float* __restrict__ B, int j, int seg, float4 v[4]) {
    const float4* c = (const float4*)(B + j * LDB + (seg << 4));
    v[0] = c[0]; v[1] = c[1]; v[2] = c[2]; v[3] = c[3];
    float n = v[0].x * v[0].x;
    n = fmaf(v[0].y, v[0].y, n); n = fmaf(v[0].z, v[0].z, n); n = fmaf(v[0].w, v[0].w, n);
    n = fmaf(v[1].x, v[1].x, n); n = fmaf(v[1].y, v[1].y, n); n = fmaf(v[1].z, v[1].z, n); n = fmaf(v[1].w, v[1].w, n);
    n = fmaf(v[2].x, v[2].x, n); n = fmaf(v[2].y, v[2].y, n); n = fmaf(v[2].z, v[2].z, n); n = fmaf(v[2].w, v[2].w, n);
    n = fmaf(v[3].x, v[3].x, n); n = fmaf(v[3].y, v[3].y, n); n = fmaf(v[3].z, v[3].z, n); n = fmaf(v[3].w, v[3].w, n);
    n += __shfl_xor_sync(0xffffffffu, n, 1);
    n += __shfl_xor_sync(0xffffffffu, n, 2);
    return n;
}

__device__ __forceinline__ void scale_store(float* __restrict__ D, int j, int seg,
                                            const float4 v[4], float f) {
    float4* d = (float4*)(D + j * LDB + (seg << 4));
    d[0] = make_float4(f * v[0].x, f * v[0].y, f * v[0].z, f * v[0].w);
    d[1] = make_float4(f * v[1].x, f * v[1].y, f * v[1].z, f * v[1].w);
    d[2] = make_float4(f * v[2].x, f * v[2].y, f * v[2].z, f * v[2].w);
    d[3] = make_float4(f * v[3].x, f * v[3].y, f * v[3].z, f * v[3].w);
}

// ---------------- octet rotation step (one matrix) ----------------
__device__ __forceinline__ void rot_step(float* __restrict__ B, float* __restrict__ nbuf,
                                         int p, int q, int o0, int o1, int tid) {
    float* bp = B + p * LDB;
    float* bq = B + q * LDB;
    ulonglong2 P0 = *(ulonglong2*)(bp + o0), P1 = *(ulonglong2*)(bp + o1);
    ulonglong2 Q0 = *(ulonglong2*)(bq + o0), Q1 = *(ulonglong2*)(bq + o1);
    u64 spq = mul2(P0.x, Q0.x);
    spq = fma2(P0.y, Q0.y, spq); spq = fma2(P1.x, Q1.x, spq); spq = fma2(P1.y, Q1.y, spq);
    float a0, a1;
    up2(spq, a0, a1);
    float apq = a0 + a1;
    apq += __shfl_xor_sync(0xffffffffu, apq, 1);
    apq += __shfl_xor_sync(0xffffffffu, apq, 2);
    apq += __shfl_xor_sync(0xffffffffu, apq, 4);
    float app = nbuf[p], aqq = nbuf[q];
    if (apq * apq > SKIP_TAU * SKIP_TAU * app * aqq) {
        float zeta = (aqq - app) / (2.0f * apq);
        float t = copysignf(1.0f, zeta) / (fabsf(zeta) + sqrtf(fmaf(zeta, zeta, 1.0f)));
        float c = rsqrtf(fmaf(t, t, 1.0f));
        float s = t * c;
        u64 c2 = pk2(c, c), s2 = pk2(s, s), ns2 = pk2(-s, -s);
        ulonglong2 NP0, NP1, NQ0, NQ1;
        NP0.x = fma2(c2, P0.x, mul2(ns2, Q0.x));
        NP0.y = fma2(c2, P0.y, mul2(ns2, Q0.y));
        NP1.x = fma2(c2, P1.x, mul2(ns2, Q1.x));
        NP1.y = fma2(c2, P1.y, mul2(ns2, Q1.y));
        NQ0.x = fma2(s2, P0.x, mul2(c2, Q0.x));
        NQ0.y = fma2(s2, P0.y, mul2(c2, Q0.y));
        NQ1.x = fma2(s2, P1.x, mul2(c2, Q1.x));
        NQ1.y = fma2(s2, P1.y, mul2(c2, Q1.y));
        *(ulonglong2*)(bp + o0) = NP0; *(ulonglong2*)(bp + o1) = NP1;
        *(ulonglong2*)(bq + o0) = NQ0; *(ulonglong2*)(bq + o1) = NQ1;
        if ((tid & 7) == 0) {
            float d = t * apq;
            nbuf[p] = app - d;
            nbuf[q] = aqq + d;
        }
    }
}

// ---------------- single-matrix one-sided Jacobi (side kernels) ----------------
__device__ void jacobi_onesided(float* __restrict__ B, float* __restrict__ nbuf, int sweeps) {
    const int tid = threadIdx.x;
    const int k = tid >> 3;
    const int o0 = (tid & 7) << 2;
    const int o1 = 32 + o0;
    const int jn = tid >> 2, segn = tid & 3;
    for (int sw = 0; sw < sweeps; ++sw) {
        {
            float4 v[4];
            float n = colnrm2(B, jn, segn, v);
            if (segn == 0) nbuf[jn] = n;
        }
        __syncthreads();
        int p = (k == 0) ? 0 : k;
        int q = 63 - k;
        for (int rr = 0; rr < 63; ++rr) {
            rot_step(B, nbuf, p, q, o0, o1, tid);
            if (k) p = (p == 63) ? 1 : p + 1;
            q = (q == 63) ? 1 : q + 1;
            __syncthreads();
        }
    }
}

// ---------------- dual-matrix one-sided Jacobi: sequential per-round, 1 barrier ----------------
__device__ void jacobi2(float* __restrict__ BA, float* __restrict__ BB,
                        float* __restrict__ nbA, float* __restrict__ nbB, int sweeps) {
    const int tid = threadIdx.x;
    const int k = tid >> 3;
    const int o0 = (tid & 7) << 2;
    const int o1 = 32 + o0;
    const int jn = tid >> 2, segn = tid & 3;
    for (int sw = 0; sw < sweeps; ++sw) {
        {
            float4 v[4];
            float nA = colnrm2(BA, jn, segn, v);
            float nB = colnrm2(BB, jn, segn, v);
            if (segn == 0) { nbA[jn] = nA; nbB[jn] = nB; }
        }
        __syncthreads();
        int p = (k == 0) ? 0 : k;
        int q = 63 - k;
        for (int rr = 0; rr < 63; ++rr) {
            rot_step(BA, nbA, p, q, o0, o1, tid);
            rot_step(BB, nbB, p, q, o0, o1, tid);
            if (k) p = (p == 63) ? 1 : p + 1;
            q = (q == 63) ? 1 : q + 1;
            __syncthreads();
        }
    }
}

// ---------------- two-sided Jacobi (only for indefinite tmean) ----------------
__device__ void jacobi_twosided(float* __restrict__ A, float* __restrict__ VT,
                                float* cbuf, float* sbuf, int sweeps) {
    const int tid = threadIdx.x;
    for (int idx = tid; idx < NN; idx += 256) {
        int r = idx >> 6, c = idx & 63;
        VT[r * LDB + c] = (r == c) ? 1.f : 0.f;
    }
    __syncthreads();
    for (int sw = 0; sw < sweeps; ++sw) {
        for (int rr = 0; rr < 63; ++rr) {
            if (tid < 32) {
                int p = (tid == 0) ? 0 : 1 + (tid - 1 + rr) % 63;
                int q = 1 + (62 - tid + rr) % 63;
                float app = A[p * LDB + p], aqq = A[q * LDB + q], apq = A[p * LDB + q];
                float c, s;
                if (fabsf(apq) > 1e-30f) {
                    float th = 0.5f * (aqq - app) / apq;
                    float t = copysignf(1.f, th) / (fabsf(th) + sqrtf(fmaf(th, th, 1.f)));
                    c = rsqrtf(fmaf(t, t, 1.f)); s = t * c;
                } else { c = 1.f; s = 0.f; }
                cbuf[tid] = c; sbuf[tid] = s;
            }
            __syncthreads();
            for (int u = tid; u < 1536; u += 256) {
                if (u < 1024) {
                    int ki = u & 31, kj = u >> 5;
                    int pi = (ki == 0) ? 0 : 1 + (ki - 1 + rr) % 63, qi = 1 + (62 - ki + rr) % 63;
                    int pj = (kj == 0) ? 0 : 1 + (kj - 1 + rr) % 63, qj = 1 + (62 - kj + rr) % 63;
                    float ci = cbuf[ki], si = sbuf[ki], cj = cbuf[kj], sj = sbuf[kj];
                    float a00 = A[pi * LDB + pj], a01 = A[pi * LDB + qj];
                    float a10 = A[qi * LDB + pj], a11 = A[qi * LDB + qj];
                    float b00 = ci * a00 - si * a10, b01 = ci * a01 - si * a11;
                    float b10 = si * a00 + ci * a10, b11 = si * a01 + ci * a11;
                    A[pi * LDB + pj] = cj * b00 - sj * b01;
                    A[pi * LDB + qj] = sj * b00 + cj * b01;
                    A[qi * LDB + pj] = cj * b10 - sj * b11;
                    A[qi * LDB + qj] = sj * b10 + cj * b11;
                } else {
                    int w = u - 1024;
                    int kk = w >> 4, c4 = (w & 15) << 2;
                    int p = (kk == 0) ? 0 : 1 + (kk - 1 + rr) % 63, q = 1 + (62 - kk + rr) % 63;
                    float c = cbuf[kk], s = sbuf[kk];
                    float4 vp = *(float4*)&VT[p * LDB + c4];
                    float4 vq = *(float4*)&VT[q * LDB + c4];
                    float4 np, nq;
                    np.x = c*vp.x - s*vq.x; np.y = c*vp.y - s*vq.y; np.z = c*vp.z - s*vq.z; np.w = c*vp.w - s*vq.w;
                    nq.x = s*vp.x + c*vq.x; nq.y = s*vp.y + c*vq.y; nq.z = s*vp.z + c*vq.z; nq.w = s*vp.w + c*vq.w;
                    *(float4*)&VT[p * LDB + c4] = np;
                    *(float4*)&VT[q * LDB + c4] = nq;
                }
            }
            __syncthreads();
        }
    }
}

// ---------------- kernel 0: arithmetic mean ----------------
__global__ __launch_bounds__(256) void mean_partial_kernel(const float* __restrict__ x) {
    const int g = blockIdx.x, tid = threadIdx.x;
    float4 acc[4] = {{0,0,0,0},{0,0,0,0},{0,0,0,0},{0,0,0,0}};
    const float4* xb = (const float4*)(x + (size_t)g * K0_NB * NN);
    for (int b = 0; b < K0_NB; ++b) {
#pragma unroll
        for (int i = 0; i < 4; ++i) {
            float4 v = xb[(size_t)b * 1024 + tid + (i << 8)];
            acc[i].x += v.x; acc[i].y += v.y; acc[i].z += v.z; acc[i].w += v.w;
        }
    }
    float4* pm = (float4*)(g_partial_mean + (size_t)g * NN);
#pragma unroll
    for (int i = 0; i < 4; ++i) pm[tid + (i << 8)] = acc[i];
}

__global__ void reduce_mean_kernel() {
    int j = blockIdx.x * 128 + threadIdx.x;
    float acc = 0.f;
    for (int g = 0; g < K0_BLOCKS; ++g) acc += g_partial_mean[(size_t)g * NN + j];
    g_mean[j] = acc * (1.0f / BATCH);
}

// ---------------- kernel 1: eigh(mean)->s,si ; eigh(G)->gsqrt ----------------
__global__ __launch_bounds__(256) void prep_kernel(const float* __restrict__ G) {
    extern __shared__ float sm[];
    float* A    = sm;
    float* Bsc  = A + 4352;
    float* nbuf = Bsc + 4352;
    const int tid = threadIdx.x;
    load_tile(blockIdx.x == 0 ? g_mean : G, A);
    __syncthreads();
    jacobi_onesided(A, nbuf, SWEEPS_SMALL);
    const int j = tid >> 2, seg = tid & 3;
    float4 v[4];
    float n = colnrm2(A, j, seg, v);
    float lam = fmaxf(sqrtf(n), EPSF);
    float inv_n = 1.0f / n;
    scale_store(Bsc, j, seg, v, sqrtf(lam) * inv_n);
    __syncthreads();
    gram_t4(Bsc, A, blockIdx.x == 0 ? g_s : g_gsqrt, 64);
    if (blockIdx.x == 0) {
        __syncthreads();
        scale_store(Bsc, j, seg, v, rsqrtf(lam) * inv_n);
        __syncthreads();
        gram_t4(Bsc, A, g_si, 64);
    }
}

// ---------------- kernel 2: per-batch logm(si x si), dual Jacobi, 3 tiles ----------------
__global__ __launch_bounds__(256, 4) void batch_log_kernel(const float* __restrict__ x) {
    extern __shared__ float sm[];
    float* T0  = sm;             // sis (persistent)
    float* T1  = T0 + 4352;      // B-matrix path (in-place sandwich)
    float* T2  = T1 + 4352;      // A-matrix path
    float* nbA = T2 + 4352;      // 64
    float* nbB = nbA + 64;       // 64
    const int tid = threadIdx.x;
    load_tile(g_si, T0);
    __syncthreads();
    const int r0 = (tid >> 4) << 2, c0 = (tid & 15) << 2;
    const int j = tid >> 2, seg = tid & 3;
    u64 tacc[8];
#pragma unroll
    for (int i = 0; i < 8; ++i) tacc[i] = 0ull;

    for (int m = 0; m < K2_NB; m += 2) {
        const float* xbA = x + ((size_t)blockIdx.x * K2_NB + m) * NN;
        const float* xbB = xbA + NN;
        // A-matrix: xA -> T2 (scratch path through T1)
        load_tile(xbA, T2);
        __syncthreads();
        mm64_t4(T0, T2, T1, LDB);  __syncthreads();   // P = si @ xA -> T1
        mm64_t4(T1, T0, T2, LDB);  __syncthreads();   // A = P @ si -> T2 (xA dead)
        // B-matrix: xB -> T1, in-place sandwich (T1 = si @ T1 @ si)
        load_tile(xbB, T1);
        __syncthreads();
        mm64_t4_ip(T0, T1);        __syncthreads();   // T1 = si @ xB   (register-staged)
        // second product: B = P @ si, i.e. T1 = T1 @ T0 (in place, staged)
        {
            u64 acc[8];
#pragma unroll
            for (int i = 0; i < 8; ++i) acc[i] = 0ull;
#pragma unroll 4
            for (int k = 0; k < 64; ++k) {
                float a0 = T1[r0 * LDB + k],       a1 = T1[(r0 + 1) * LDB + k];
                float a2 = T1[(r0 + 2) * LDB + k], a3 = T1[(r0 + 3) * LDB + k];
                ulonglong2 b = *(const ulonglong2*)&T0[k * LDB + c0];
                u64 p;
                p = pk2(a0, a0); acc[0] = fma2(p, b.x, acc[0]); acc[1] = fma2(p, b.y, acc[1]);
                p = pk2(a1, a1); acc[2] = fma2(p, b.x, acc[2]); acc[3] = fma2(p, b.y, acc[3]);
                p = pk2(a2, a2); acc[4] = fma2(p, b.x, acc[4]); acc[5] = fma2(p, b.y, acc[5]);
                p = pk2(a3, a3); acc[6] = fma2(p, b.x, acc[6]); acc[7] = fma2(p, b.y, acc[7]);
            }
            __syncthreads();
#pragma unroll
            for (int i = 0; i < 4; ++i)
                *(ulonglong2*)&T1[(r0 + i) * LDB + c0] = make_ulonglong2(acc[2 * i], acc[2 * i + 1]);
            __syncthreads();
        }
        // dual Jacobi on A (T2) and B (T1)
        jacobi2(T2, T1, nbA, nbB, SWEEPS_BATCH);
        // log factors
        {
            float4 v[4];
            float nA = colnrm2(T2, j, seg, v);
            float nB = colnrm2(T1, j, seg, v);
            if (seg == 0) {
                nbA[j] = logf(fmaxf(sqrtf(nA), EPSF)) / nA;
                nbB[j] = logf(fmaxf(sqrtf(nB), EPSF)) / nB;
            }
        }
        __syncthreads();
        // tacc += sum_j fA_j bA_j bA_j^T + fB_j bB_j bB_j^T
#pragma unroll 4
        for (int jj = 0; jj < 64; ++jj) {
            float f = nbA[jj];
            float4 u = *(const float4*)&T2[jj * LDB + r0];
            ulonglong2 b = *(const ulonglong2*)&T2[jj * LDB + c0];
            u64 p;
            p = pk2(f * u.x, f * u.x); tacc[0] = fma2(p, b.x, tacc[0]); tacc[1] = fma2(p, b.y, tacc[1]);
            p = pk2(f * u.y, f * u.y); tacc[2] = fma2(p, b.x, tacc[2]); tacc[3] = fma2(p, b.y, tacc[3]);
            p = pk2(f * u.z, f * u.z); tacc[4] = fma2(p, b.x, tacc[4]); tacc[5] = fma2(p, b.y, tacc[5]);
            p = pk2(f * u.w, f * u.w); tacc[6] = fma2(p, b.x, tacc[6]); tacc[7] = fma2(p, b.y, tacc[7]);
        }
#pragma unroll 4
        for (int jj = 0; jj < 64; ++jj) {
            float f = nbB[jj];
            float4 u = *(const float4*)&T1[jj * LDB + r0];
            ulonglong2 b = *(const ulonglong2*)&T1[jj * LDB + c0];
            u64 p;
            p = pk2(f * u.x, f * u.x); tacc[0] = fma2(p, b.x, tacc[0]); tacc[1] = fma2(p, b.y, tacc[1]);
            p = pk2(f * u.y, f * u.y); tacc[2] = fma2(p, b.x, tacc[2]); tacc[3] = fma2(p, b.y, tacc[3]);
            p = pk2(f * u.z, f * u.z); tacc[4] = fma2(p, b.x, tacc[4]); tacc[5] = fma2(p, b.y, tacc[5]);
            p = pk2(f * u.w, f * u.w); tacc[6] = fma2(p, b.x, tacc[6]); tacc[7] = fma2(p, b.y, tacc[7]);
        }
        __syncthreads();
    }
    float* pt = g_partial_t + (size_t)blockIdx.x * NN;
#pragma unroll
    for (int i = 0; i < 4; ++i)
        *(ulonglong2*)&pt[(r0 + i) * 64 + c0] = make_ulonglong2(tacc[2 * i], tacc[2 * i + 1]);
}

__global__ void reduce_t_kernel() {
    int j = blockIdx.x * 128 + threadIdx.x;
    float acc = 0.f;
    for (int g = 0; g < K2_BLOCKS; ++g) acc += g_partial_t[(size_t)g * NN + j];
    g_tmean[j] = acc * (1.0f / BATCH);
}

// ---------------- kernel 3: expm(tmean), center, csi, W, WT ----------------
__global__ __launch_bounds__(256) void center_kernel() {
    extern __shared__ float sm[];
    float* A  = sm;
    float* VT = A + 4352;
    float* T1 = VT + 4352;
    float* T2 = T1 + 4352;
    float* fw = T2 + 4352;
    float* cb = fw + 64;
    float* sb = cb + 32;
    float* nbuf = sb + 32;
    const int tid = threadIdx.x;

    load_tile(g_tmean, A);
    __syncthreads();
    jacobi_twosided(A, VT, cb, sb, SWEEPS_TS);
    if (tid < 64) fw[tid] = expf(A[tid * LDB + tid]);
    __syncthreads();
    for (int idx = tid; idx < NN; idx += 256) {
        int k2 = idx >> 6, i = idx & 63;
        T1[k2 * LDB + i] = fw[k2] * VT[k2 * LDB + i];
    }
    __syncthreads();
    gram_t4(T1, VT, T2, LDB);           // T2 = expm(tmean)
    __syncthreads();
    load_tile(g_s, A);
    __syncthreads();
    mm64_t4(A, T2, T1, LDB);  __syncthreads();  // T1 = s E
    mm64_t4(T1, A, T2, LDB);  __syncthreads();  // T2 = center (SPD)
    jacobi_onesided(T2, nbuf, SWEEPS_SMALL);
    {
        const int j = tid >> 2, seg = tid & 3;
        float4 v[4];
        float n = colnrm2(T2, j, seg, v);
        float lam = fmaxf(sqrtf(n), EPSF);
        float f = rsqrtf(lam) / n;
        scale_store(T1, j, seg, v, f);
    }
    __syncthreads();
    gram_t4(T1, T2, A, LDB);            // A = csi
    __syncthreads();
    load_tile(g_gsqrt, VT);
    __syncthreads();
    mm64_t4(VT, A, T1, LDB);            // T1 = g_sqrt @ csi = W
    __syncthreads();
    store_tile(T1, g_W);
    for (int idx = tid; idx < NN; idx += 256) {
        int rr = idx >> 6, cc = idx & 63;
        g_WT[(cc << 6) + rr] = T1[rr * LDB + cc];
    }
}

// ---------------- kernel 4: out_b = W x_b W^T ----------------
__global__ __launch_bounds__(256) void output_kernel(const float* __restrict__ x,
                                                     float* __restrict__ out) {
    extern __shared__ float sm[];
    float* Ws = sm;
    float* WT = Ws + 4352;
    float* xs = WT + 4352;
    float* P  = xs + 4352;
    load_tile(g_W, Ws);
    load_tile(g_WT, WT);
    load_tile(x + (size_t)blockIdx.x * NN, xs);
    __syncthreads();
    mm64_t4(Ws, xs, P, LDB);            // P = W @ x
    __syncthreads();
    mm64_t4(P, WT, out + (size_t)blockIdx.x * NN, 64);  // out = P @ W^T
}

// ---------------- launcher ----------------
extern "C" void kernel_launch(void* const* d_in, const int* in_sizes, int n_in,
                              void* d_out, int out_size) {
    const float* x;
    const float* G;
    if (in_sizes[0] == NN) { G = (const float*)d_in[0]; x = (const float*)d_in[1]; }
    else                   { x = (const float*)d_in[0]; G = (const float*)d_in[1]; }
    float* out = (float*)d_out;

    constexpr size_t SM_PREP   = (size_t)(2 * 4352 + 64) * 4;
    constexpr size_t SM_BATCH  = (size_t)(3 * 4352 + 128) * 4;
    constexpr size_t SM_CENTER = (size_t)(4 * 4352 + 64 + 32 + 32 + 64) * 4;
    constexpr size_t SM_OUT    = (size_t)(4 * 4352) * 4;

    cudaFuncSetAttribute(batch_log_kernel, cudaFuncAttributeMaxDynamicSharedMemorySize, (int)SM_BATCH);
    cudaFuncSetAttribute(center_kernel,    cudaFuncAttributeMaxDynamicSharedMemorySize, (int)SM_CENTER);
    cudaFuncSetAttribute(output_kernel,    cudaFuncAttributeMaxDynamicSharedMemorySize, (int)SM_OUT);

    mean_partial_kernel<<<K0_BLOCKS, 256>>>(x);
    reduce_mean_kernel<<<32, 128>>>();
    prep_kernel<<<2, 256, SM_PREP>>>(G);
    batch_log_kernel<<<K2_BLOCKS, 256, SM_BATCH>>>(x);
    reduce_t_kernel<<<32, 128>>>();
    center_kernel<<<1, 256, SM_CENTER>>>();
    output_kernel<<<BATCH, 256, SM_OUT>>>(x, out);
}

// round 11
// speedup vs baseline: 1.1361x; 1.0578x over previous
#include <cuda_runtime.h>
#include <math.h>
#include <stdint.h>

#define BATCH 8192
#define NN 4096
#define LDB 68           // padded stride (floats), float4-aligned
#define EPSF 1e-8f
#define SKIP_TAU 1e-6f

#define K0_BLOCKS 256
#define K0_NB 32
#define K2_BLOCKS 2048   // x4 matrices per block (2 per 128-thread group)
#define SWEEPS_BATCH 7
#define SWEEPS_SMALL 8

// ---------------- device scratch ----------------
__device__ __align__(256) float g_partial_mean[(size_t)K0_BLOCKS * NN];
__device__ __align__(256) float g_mean[NN];
__device__ __align__(256) float g_s[NN];
__device__ __align__(256) float g_si[NN];
__device__ __align__(256) float g_gsqrt[NN];
__device__ __align__(256) float g_W[NN];
__device__ __align__(256) float g_WT[NN];
__device__ __align__(256) float g_partial_t[(size_t)BATCH * NN];
__device__ __align__(256) float g_tmean[NN];

// ---------------- packed f32x2 helpers ----------------
typedef unsigned long long u64;
__device__ __forceinline__ u64 pk2(float x, float y) {
    u64 r; asm("mov.b64 %0,{%1,%2};" : "=l"(r) : "f"(x), "f"(y)); return r;
}
__device__ __forceinline__ void up2(u64 v, float& x, float& y) {
    asm("mov.b64 {%0,%1},%2;" : "=f"(x), "=f"(y) : "l"(v));
}
__device__ __forceinline__ u64 fma2(u64 a, u64 b, u64 c) {
    u64 d; asm("fma.rn.f32x2 %0,%1,%2,%3;" : "=l"(d) : "l"(a), "l"(b), "l"(c)); return d;
}
__device__ __forceinline__ u64 mul2(u64 a, u64 b) {
    u64 d; asm("mul.rn.f32x2 %0,%1,%2;" : "=l"(d) : "l"(a), "l"(b)); return d;
}
// named barrier over a 128-thread group
__device__ __forceinline__ void barg(int id) {
    asm volatile("bar.sync %0, 128;" :: "r"(id) : "memory");
}

// ---------------- 256-thread helpers (side kernels) ----------------
__device__ __forceinline__ void load_tile(const float* __restrict__ g, float* __restrict__ s) {
    for (int i = threadIdx.x; i < 1024; i += 256) {
        int r = i >> 4, c4 = (i & 15) << 2;
        *(float4*)&s[r * LDB + c4] = *(const float4*)&g[(r << 6) + c4];
    }
}
__device__ __forceinline__ void store_tile(const float* __restrict__ s, float* __restrict__ g) {
    for (int i = threadIdx.x; i < 1024; i += 256) {
        int r = i >> 4, c4 = (i & 15) << 2;
        *(float4*)&g[(r << 6) + c4] = *(const float4*)&s[r * LDB + c4];
    }
}

__device__ __forceinline__ void mm64_t4(const float* __restrict__ A, const float* __restrict__ B,
                                        float* __restrict__ C, int cstride) {
    const int r0 = (threadIdx.x >> 4) << 2;
    const int c0 = (threadIdx.x & 15) << 2;
    u64 acc[8];
#pragma unroll
    for (int i = 0; i < 8; ++i) acc[i] = 0ull;
#pragma unroll 4
    for (int k = 0; k < 64; ++k) {
        float a0 = A[r0 * LDB + k],       a1 = A[(r0 + 1) * LDB + k];
        float a2 = A[(r0 + 2) * LDB + k], a3 = A[(r0 + 3) * LDB + k];
        ulonglong2 b = *(const ulonglong2*)&B[k * LDB + c0];
        u64 p;
        p = pk2(a0, a0); acc[0] = fma2(p, b.x, acc[0]); acc[1] = fma2(p, b.y, acc[1]);
        p = pk2(a1, a1); acc[2] = fma2(p, b.x, acc[2]); acc[3] = fma2(p, b.y, acc[3]);
        p = pk2(a2, a2); acc[4] = fma2(p, b.x, acc[4]); acc[5] = fma2(p, b.y, acc[5]);
        p = pk2(a3, a3); acc[6] = fma2(p, b.x, acc[6]); acc[7] = fma2(p, b.y, acc[7]);
    }
#pragma unroll
    for (int i = 0; i < 4; ++i)
        *(ulonglong2*)&C[(r0 + i) * cstride + c0] = make_ulonglong2(acc[2 * i], acc[2 * i + 1]);
}

__device__ __forceinline__ void gram_t4(const float* __restrict__ Bs, const float* __restrict__ B,
                                        float* __restrict__ out, int ostride) {
    const int r0 = (threadIdx.x >> 4) << 2;
    const int c0 = (threadIdx.x & 15) << 2;
    u64 acc[8];
#pragma unroll
    for (int i = 0; i < 8; ++i) acc[i] = 0ull;
#pragma unroll 4
    for (int j = 0; j < 64; ++j) {
        float4 u = *(const float4*)&Bs[j * LDB + r0];
        ulonglong2 b = *(const ulonglong2*)&B[j * LDB + c0];
        u64 p;
        p = pk2(u.x, u.x); acc[0] = fma2(p, b.x, acc[0]); acc[1] = fma2(p, b.y, acc[1]);
        p = pk2(u.y, u.y); acc[2] = fma2(p, b.x, acc[2]); acc[3] = fma2(p, b.y, acc[3]);
        p = pk2(u.z, u.z); acc[4] = fma2(p, b.x, acc[4]); acc[5] = fma2(p, b.y, acc[5]);
        p = pk2(u.w, u.w); acc[6] = fma2(p, b.x, acc[6]); acc[7] = fma2(p, b.y, acc[7]);
    }
#pragma unroll
    for (int i = 0; i < 4; ++i)
        *(ulonglong2*)&out[(r0 + i) * ostride + c0] = make_ulonglong2(acc[2 * i], acc[2 * i + 1]);
}

__device__ __forceinline__ float colnrm2(const float* __restrict__ B, int j, int seg, float4 v[4]) {
    const float4* c = (const float4*)(B + j * LDB + (seg << 4));
    v[0] = c[0]; v[1] = c[1]; v[2] = c[2]; v[3] = c[3];
    float n = v[0].x * v[0].x;
    n = fmaf(v[0].y, v[0].y, n); n = fmaf(v[0].z, v[0].z, n); n = fmaf(v[0].w, v[0].w, n);
    n = fmaf(v[1].x, v[1].x, n); n = fmaf(v[1].y, v[1].y, n); n = fmaf(v[1].z, v[1].z, n); n = fmaf(v[1].w, v[1].w, n);
    n = fmaf(v[2].x, v[2].x, n); n = fmaf(v[2].y, v[2].y, n); n = fmaf(v[2].z, v[2].z, n); n = fmaf(v[2].w, v[2].w, n);
    n = fmaf(v[3].x, v[3].x, n); n = fmaf(v[3].y, v[3].y, n); n = fmaf(v[3].z, v[3].z, n); n = fmaf(v[3].w, v[3].w, n);
    n += __shfl_xor_sync(0xffffffffu, n, 1);
    n += __shfl_xor_sync(0xffffffffu, n, 2);
    return n;
}

__device__ __forceinline__ void scale_store(float* __restrict__ D, int j, int seg,
                                            const float4 v[4], float f) {
    float4* d = (float4*)(D + j * LDB + (seg << 4));
    d[0] = make_float4(f * v[0].x, f * v[0].y, f * v[0].z, f * v[0].w);
    d[1] = make_float4(f * v[1].x, f * v[1].y, f * v[1].z, f * v[1].w);
    d[2] = make_float4(f * v[2].x, f * v[2].y, f * v[2].z, f * v[2].w);
    d[3] = make_float4(f * v[3].x, f * v[3].y, f * v[3].z, f * v[3].w);
}

// ---------------- octet rotation step (shared by all Jacobi variants) ----------------
__device__ __forceinline__ void rot_step(float* __restrict__ B, float* __restrict__ nbuf,
                                         int p, int q, int o0, int o1, int lt) {
    float* bp = B + p * LDB;
    float* bq = B + q * LDB;
    ulonglong2 P0 = *(ulonglong2*)(bp + o0), P1 = *(ulonglong2*)(bp + o1);
    ulonglong2 Q0 = *(ulonglong2*)(bq + o0), Q1 = *(ulonglong2*)(bq + o1);
    u64 spq = mul2(P0.x, Q0.x);
    spq = fma2(P0.y, Q0.y, spq); spq = fma2(P1.x, Q1.x, spq); spq = fma2(P1.y, Q1.y, spq);
    float a0, a1;
    up2(spq, a0, a1);
    float apq = a0 + a1;
    apq += __shfl_xor_sync(0xffffffffu, apq, 1);
    apq += __shfl_xor_sync(0xffffffffu, apq, 2);
    apq += __shfl_xor_sync(0xffffffffu, apq, 4);
    float app = nbuf[p], aqq = nbuf[q];
    if (apq * apq > SKIP_TAU * SKIP_TAU * app * aqq) {
        float zeta = (aqq - app) / (2.0f * apq);
        float t = copysignf(1.0f, zeta) / (fabsf(zeta) + sqrtf(fmaf(zeta, zeta, 1.0f)));
        float c = rsqrtf(fmaf(t, t, 1.0f));
        float s = t * c;
        u64 c2 = pk2(c, c), s2 = pk2(s, s), ns2 = pk2(-s, -s);
        ulonglong2 NP0, NP1, NQ0, NQ1;
        NP0.x = fma2(c2, P0.x, mul2(ns2, Q0.x));
        NP0.y = fma2(c2, P0.y, mul2(ns2, Q0.y));
        NP1.x = fma2(c2, P1.x, mul2(ns2, Q1.x));
        NP1.y = fma2(c2, P1.y, mul2(ns2, Q1.y));
        NQ0.x = fma2(s2, P0.x, mul2(c2, Q0.x));
        NQ0.y = fma2(s2, P0.y, mul2(c2, Q0.y));
        NQ1.x = fma2(s2, P1.x, mul2(c2, Q1.x));
        NQ1.y = fma2(s2, P1.y, mul2(c2, Q1.y));
        *(ulonglong2*)(bp + o0) = NP0; *(ulonglong2*)(bp + o1) = NP1;
        *(ulonglong2*)(bq + o0) = NQ0; *(ulonglong2*)(bq + o1) = NQ1;
        if ((lt & 7) == 0) {
            float d = t * apq;
            nbuf[p] = app - d;
            nbuf[q] = aqq + d;
        }
    }
}

// ---------------- 256-thread one-sided Jacobi (side kernels) ----------------
__device__ void jacobi_onesided(float* __restrict__ B, float* __restrict__ nbuf, int sweeps) {
    const int tid = threadIdx.x;
    const int k = tid >> 3;
    const int o0 = (tid & 7) << 2;
    const int o1 = 32 + o0;
    const int jn = tid >> 2, segn = tid & 3;
    for (int sw = 0; sw < sweeps; ++sw) {
        {
            float4 v[4];
            float n = colnrm2(B, jn, segn, v);
            if (segn == 0) nbuf[jn] = n;
        }
        __syncthreads();
        int p = (k == 0) ? 0 : k;
        int q = 63 - k;
        for (int rr = 0; rr < 63; ++rr) {
            rot_step(B, nbuf, p, q, o0, o1, tid);
            if (k) p = (p == 63) ? 1 : p + 1;
            q = (q == 63) ? 1 : q + 1;
            __syncthreads();
        }
    }
}

// ---------------- 128-thread group Jacobi: 16 octets x 2 pairs, named barrier ----------------
__device__ void jacobi_g(float* __restrict__ B, float* __restrict__ nb,
                         int gt, int bid, int sweeps) {
    const int o  = gt >> 3;              // 0..15
    const int o0 = (gt & 7) << 2;
    const int o1 = 32 + o0;
    const int jn = gt >> 1;
    const int segb = (gt & 1) << 5;
    for (int sw = 0; sw < sweeps; ++sw) {
        {   // refresh norms: 2 threads per column
            const float4* cc = (const float4*)(B + jn * LDB + segb);
            float n = 0.f;
#pragma unroll
            for (int i = 0; i < 8; ++i) {
                float4 v = cc[i];
                n = fmaf(v.x, v.x, n); n = fmaf(v.y, v.y, n);
                n = fmaf(v.z, v.z, n); n = fmaf(v.w, v.w, n);
            }
            n += __shfl_xor_sync(0xffffffffu, n, 1);
            if ((gt & 1) == 0) nb[jn] = n;
        }
        barg(bid);
        int p1 = (o == 0) ? 0 : o, q1 = 63 - o;
        int p2 = o + 16,           q2 = 47 - o;
        for (int rr = 0; rr < 63; ++rr) {
            rot_step(B, nb, p1, q1, o0, o1, gt);
            rot_step(B, nb, p2, q2, o0, o1, gt);
            if (o) p1 = (p1 == 63) ? 1 : p1 + 1;
            q1 = (q1 == 63) ? 1 : q1 + 1;
            p2 = (p2 == 63) ? 1 : p2 + 1;
            q2 = (q2 == 63) ? 1 : q2 + 1;
            barg(bid);
        }
    }
}

// ---------------- 128-thread in-place matmuls (column/row-blocked) ----------------
// X <- A @ X (reads columns of X per output column: column blocks independent)
__device__ __forceinline__ void mmip_left(const float* __restrict__ A, float* __restrict__ X,
                                          int gt, int bid) {
    const int r0 = (gt >> 3) << 2;          // 16 groups x 4 rows = 64
    const int cc = (gt & 7) << 2;           // 8 groups x 4 cols = 32 per block
#pragma unroll
    for (int cb = 0; cb < 2; ++cb) {
        const int c0 = (cb << 5) + cc;
        u64 acc[8];
#pragma unroll
        for (int i = 0; i < 8; ++i) acc[i] = 0ull;
#pragma unroll 4
        for (int k = 0; k < 64; ++k) {
            float a0 = A[r0 * LDB + k],       a1 = A[(r0 + 1) * LDB + k];
            float a2 = A[(r0 + 2) * LDB + k], a3 = A[(r0 + 3) * LDB + k];
            ulonglong2 b = *(const ulonglong2*)&X[k * LDB + c0];
            u64 p;
            p = pk2(a0, a0); acc[0] = fma2(p, b.x, acc[0]); acc[1] = fma2(p, b.y, acc[1]);
            p = pk2(a1, a1); acc[2] = fma2(p, b.x, acc[2]); acc[3] = fma2(p, b.y, acc[3]);
            p = pk2(a2, a2); acc[4] = fma2(p, b.x, acc[4]); acc[5] = fma2(p, b.y, acc[5]);
            p = pk2(a3, a3); acc[6] = fma2(p, b.x, acc[6]); acc[7] = fma2(p, b.y, acc[7]);
        }
        barg(bid);
#pragma unroll
        for (int i = 0; i < 4; ++i)
            *(ulonglong2*)&X[(r0 + i) * LDB + c0] = make_ulonglong2(acc[2 * i], acc[2 * i + 1]);
        barg(bid);
    }
}

// X <- X @ B (reads rows of X per output row: row blocks independent)
__device__ __forceinline__ void mmip_right(float* __restrict__ X, const float* __restrict__ B,
                                           int gt, int bid) {
    const int rr = (gt >> 4) << 2;          // 8 groups x 4 rows = 32 per block
    const int c0 = (gt & 15) << 2;          // 64 cols
#pragma unroll
    for (int rb = 0; rb < 2; ++rb) {
        const int r0 = (rb << 5) + rr;
        u64 acc[8];
#pragma unroll
        for (int i = 0; i < 8; ++i) acc[i] = 0ull;
#pragma unroll 4
        for (int k = 0; k < 64; ++k) {
            float a0 = X[r0 * LDB + k],       a1 = X[(r0 + 1) * LDB + k];
            float a2 = X[(r0 + 2) * LDB + k], a3 = X[(r0 + 3) * LDB + k];
            ulonglong2 b = *(const ulonglong2*)&B[k * LDB + c0];
            u64 p;
            p = pk2(a0, a0); acc[0] = fma2(p, b.x, acc[0]); acc[1] = fma2(p, b.y, acc[1]);
            p = pk2(a1, a1); acc[2] = fma2(p, b.x, acc[2]); acc[3] = fma2(p, b.y, acc[3]);
            p = pk2(a2, a2); acc[4] = fma2(p, b.x, acc[4]); acc[5] = fma2(p, b.y, acc[5]);
            p = pk2(a3, a3); acc[6] = fma2(p, b.x, acc[6]); acc[7] = fma2(p, b.y, acc[7]);
        }
        barg(bid);
#pragma unroll
        for (int i = 0; i < 4; ++i)
            *(ulonglong2*)&X[(r0 + i) * LDB + c0] = make_ulonglong2(acc[2 * i], acc[2 * i + 1]);
        barg(bid);
    }
}

// Gram to global: out[r][c] = sum_j fb_j B[j][r] B[j][c]; two half-passes of 8 regs.
__device__ __forceinline__ void gram_g(const float* __restrict__ B, const float* __restrict__ fb,
                                       float* __restrict__ out, int gt) {
    const int c0 = (gt & 15) << 2;
    const int rbase = (gt >> 4) << 3;
#pragma unroll
    for (int half = 0; half < 2; ++half) {
        const int r0 = rbase + (half << 2);
        u64 acc[8];
#pragma unroll
        for (int i = 0; i < 8; ++i) acc[i] = 0ull;
#pragma unroll 4
        for (int j = 0; j < 64; ++j) {
            float f = fb[j];
            float4 u = *(const float4*)&B[j * LDB + r0];
            ulonglong2 b = *(const ulonglong2*)&B[j * LDB + c0];
            u64 p;
            p = pk2(f * u.x, f * u.x); acc[0] = fma2(p, b.x, acc[0]); acc[1] = fma2(p, b.y, acc[1]);
            p = pk2(f * u.y, f * u.y); acc[2] = fma2(p, b.x, acc[2]); acc[3] = fma2(p, b.y, acc[3]);
            p = pk2(f * u.z, f * u.z); acc[4] = fma2(p, b.x, acc[4]); acc[5] = fma2(p, b.y, acc[5]);
            p = pk2(f * u.w, f * u.w); acc[6] = fma2(p, b.x, acc[6]); acc[7] = fma2(p, b.y, acc[7]);
        }
#pragma unroll
        for (int i = 0; i < 4; ++i)
            *(ulonglong2*)&out[(r0 + i) * 64 + c0] = make_ulonglong2(acc[2 * i], acc[2 * i + 1]);
    }
}

// ---------------- kernel 0: arithmetic mean ----------------
__global__ __launch_bounds__(256) void mean_partial_kernel(const float* __restrict__ x) {
    const int g = blockIdx.x, tid = threadIdx.x;
    float4 acc[4] = {{0,0,0,0},{0,0,0,0},{0,0,0,0},{0,0,0,0}};
    const float4* xb = (const float4*)(x + (size_t)g * K0_NB * NN);
    for (int b = 0; b < K0_NB; ++b) {
#pragma unroll
        for (int i = 0; i < 4; ++i) {
            float4 v = xb[(size_t)b * 1024 + tid + (i << 8)];
            acc[i].x += v.x; acc[i].y += v.y; acc[i].z += v.z; acc[i].w += v.w;
        }
    }
    float4* pm = (float4*)(g_partial_mean + (size_t)g * NN);
#pragma unroll
    for (int i = 0; i < 4; ++i) pm[tid + (i << 8)] = acc[i];
}

__global__ void reduce_mean_kernel() {
    int j = blockIdx.x * 128 + threadIdx.x;
    float acc = 0.f;
    for (int g = 0; g < K0_BLOCKS; ++g) acc += g_partial_mean[(size_t)g * NN + j];
    g_mean[j] = acc * (1.0f / BATCH);
}

// ---------------- kernel 1: eigh(mean)->s,si ; eigh(G)->gsqrt ----------------
__global__ __launch_bounds__(256) void prep_kernel(const float* __restrict__ G) {
    extern __shared__ float sm[];
    float* A    = sm;
    float* Bsc  = A + 4352;
    float* nbuf = Bsc + 4352;
    const int tid = threadIdx.x;
    load_tile(blockIdx.x == 0 ? g_mean : G, A);
    __syncthreads();
    jacobi_onesided(A, nbuf, SWEEPS_SMALL);
    const int j = tid >> 2, seg = tid & 3;
    float4 v[4];
    float n = colnrm2(A, j, seg, v);
    float lam = fmaxf(sqrtf(n), EPSF);
    float inv_n = 1.0f / n;
    scale_store(Bsc, j, seg, v, sqrtf(lam) * inv_n);
    __syncthreads();
    gram_t4(Bsc, A, blockIdx.x == 0 ? g_s : g_gsqrt, 64);
    if (blockIdx.x == 0) {
        __syncthreads();
        scale_store(Bsc, j, seg, v, rsqrtf(lam) * inv_n);
        __syncthreads();
        gram_t4(Bsc, A, g_si, 64);
    }
}

// ---------------- kernel 2: per-batch logm(si x si), 2 independent 128-thread groups ----------------
__global__ __launch_bounds__(256, 4) void batch_log_kernel(const float* __restrict__ x) {
    extern __shared__ float sm[];
    float* T0 = sm;                       // si (shared, read-only)
    const int tid = threadIdx.x;
    const int g = tid >> 7;
    const int gt = tid & 127;
    const int bid = g + 1;                // named barrier id
    float* T  = sm + 4352 + g * 4352;     // this group's matrix tile
    float* nb = sm + 3 * 4352 + g * 64;
    float* fb = sm + 3 * 4352 + 128 + g * 64;

    load_tile(g_si, T0);
    __syncthreads();                      // last block-wide barrier

    const int jn = gt >> 1;
    const int segb = (gt & 1) << 5;

    for (int mi = 0; mi < 2; ++mi) {
        const size_t mat = (size_t)blockIdx.x * 4 + g * 2 + mi;
        const float* xb = x + mat * NN;
        for (int i = gt; i < 1024; i += 128) {
            int r = i >> 4, c4 = (i & 15) << 2;
            *(float4*)&T[r * LDB + c4] = *(const float4*)&xb[(r << 6) + c4];
        }
        barg(bid);
        mmip_left(T0, T, gt, bid);        // T = si @ x   (in place)
        mmip_right(T, T0, gt, bid);       // T = T @ si   (in place)
        jacobi_g(T, nb, gt, bid, SWEEPS_BATCH);
        {   // log factors
            const float4* cc = (const float4*)(T + jn * LDB + segb);
            float n = 0.f;
#pragma unroll
            for (int i = 0; i < 8; ++i) {
                float4 v = cc[i];
                n = fmaf(v.x, v.x, n); n = fmaf(v.y, v.y, n);
                n = fmaf(v.z, v.z, n); n = fmaf(v.w, v.w, n);
            }
            n += __shfl_xor_sync(0xffffffffu, n, 1);
            if ((gt & 1) == 0) fb[jn] = logf(fmaxf(sqrtf(n), EPSF)) / n;
        }
        barg(bid);
        gram_g(T, fb, g_partial_t + mat * NN, gt);
        barg(bid);                        // gram reads done before next load
    }
}

__global__ void reduce_t_kernel() {
    int j = blockIdx.x * 128 + threadIdx.x;
    float acc = 0.f;
    for (int g = 0; g < BATCH; ++g) acc += g_partial_t[(size_t)g * NN + j];
    g_tmean[j] = acc * (1.0f / BATCH);
}

// ---------------- kernel 3: expm(tmean) via shifted one-sided, center, csi, W, WT ----------------
__global__ __launch_bounds__(256) void center_kernel() {
    extern __shared__ float sm[];
    float* A    = sm;
    float* T1   = A + 4352;
    float* T2   = T1 + 4352;
    float* fw   = T2 + 4352;   // 64
    float* nbuf = fw + 64;     // 64
    float* sigp = nbuf + 64;   // 1
    const int tid = threadIdx.x;
    const int j = tid >> 2, seg = tid & 3;

    load_tile(g_tmean, A);
    __syncthreads();
    // Gershgorin shift: sigma = 1.1 * max_i sum_j |t_ij| + 1e-2
    {
        const float4* c = (const float4*)(A + j * LDB + (seg << 4));
        float s = 0.f;
#pragma unroll
        for (int i = 0; i < 4; ++i) {
            float4 v = c[i];
            s += fabsf(v.x) + fabsf(v.y) + fabsf(v.z) + fabsf(v.w);
        }
        s += __shfl_xor_sync(0xffffffffu, s, 1);
        s += __shfl_xor_sync(0xffffffffu, s, 2);
        if (seg == 0) fw[j] = s;
    }
    __syncthreads();
    if (tid == 0) {
        float mx = 0.f;
        for (int i = 0; i < 64; ++i) mx = fmaxf(mx, fw[i]);
        sigp[0] = 1.1f * mx + 1e-2f;
    }
    __syncthreads();
    const float sigma = sigp[0];
    if (tid < 64) A[tid * LDB + tid] += sigma;   // M = tmean + sigma*I  (SPD)
    __syncthreads();
    jacobi_onesided(A, nbuf, SWEEPS_SMALL);
    {   // E = sum_j exp(mu_j - sigma)/mu_j^2 * b_j b_j^T
        float4 v[4];
        float n = colnrm2(A, j, seg, v);
        float mu = fmaxf(sqrtf(n), EPSF);
        float f = expf(mu - sigma) / n;
        scale_store(T1, j, seg, v, f);
    }
    __syncthreads();
    gram_t4(T1, A, T2, LDB);            // T2 = expm(tmean)
    __syncthreads();
    load_tile(g_s, A);
    __syncthreads();
    mm64_t4(A, T2, T1, LDB);  __syncthreads();  // T1 = s E
    mm64_t4(T1, A, T2, LDB);  __syncthreads();  // T2 = center (SPD)
    jacobi_onesided(T2, nbuf, SWEEPS_SMALL);
    {
        float4 v[4];
        float n = colnrm2(T2, j, seg, v);
        float lam = fmaxf(sqrtf(n), EPSF);
        float f = rsqrtf(lam) / n;
        scale_store(T1, j, seg, v, f);
    }
    __syncthreads();
    gram_t4(T1, T2, A, LDB);            // A = csi
    __syncthreads();
    load_tile(g_gsqrt, T1);
    __syncthreads();
    mm64_t4(T1, A, T2, LDB);            // T2 = g_sqrt @ csi = W
    __syncthreads();
    store_tile(T2, g_W);
    for (int idx = tid; idx < NN; idx += 256) {
        int rr = idx >> 6, cc = idx & 63;
        g_WT[(cc << 6) + rr] = T2[rr * LDB + cc];
    }
}

// ---------------- kernel 4: out_b = W x_b W^T ----------------
__global__ __launch_bounds__(256) void output_kernel(const float* __restrict__ x,
                                                     float* __restrict__ out) {
    extern __shared__ float sm[];
    float* Ws = sm;
    float* WT = Ws + 4352;
    float* xs = WT + 4352;
    float* P  = xs + 4352;
    load_tile(g_W, Ws);
    load_tile(g_WT, WT);
    load_tile(x + (size_t)blockIdx.x * NN, xs);
    __syncthreads();
    mm64_t4(Ws, xs, P, LDB);            // P = W @ x
    __syncthreads();
    mm64_t4(P, WT, out + (size_t)blockIdx.x * NN, 64);  // out = P @ W^T
}

// ---------------- launcher ----------------
extern "C" void kernel_launch(void* const* d_in, const int* in_sizes, int n_in,
                              void* d_out, int out_size) {
    const float* x;
    const float* G;
    if (in_sizes[0] == NN) { G = (const float*)d_in[0]; x = (const float*)d_in[1]; }
    else                   { x = (const float*)d_in[0]; G = (const float*)d_in[1]; }
    float* out = (float*)d_out;

    constexpr size_t SM_PREP   = (size_t)(2 * 4352 + 64) * 4;
    constexpr size_t SM_BATCH  = (size_t)(3 * 4352 + 256) * 4;
    constexpr size_t SM_CENTER = (size_t)(3 * 4352 + 64 + 64 + 4) * 4;
    constexpr size_t SM_OUT    = (size_t)(4 * 4352) * 4;

    cudaFuncSetAttribute(batch_log_kernel, cudaFuncAttributeMaxDynamicSharedMemorySize, (int)SM_BATCH);
    cudaFuncSetAttribute(center_kernel,    cudaFuncAttributeMaxDynamicSharedMemorySize, (int)SM_CENTER);
    cudaFuncSetAttribute(output_kernel,    cudaFuncAttributeMaxDynamicSharedMemorySize, (int)SM_OUT);

    mean_partial_kernel<<<K0_BLOCKS, 256>>>(x);
    reduce_mean_kernel<<<32, 128>>>();
    prep_kernel<<<2, 256, SM_PREP>>>(G);
    batch_log_kernel<<<K2_BLOCKS, 256, SM_BATCH>>>(x);
    reduce_t_kernel<<<32, 128>>>();
    center_kernel<<<1, 256, SM_CENTER>>>();
    output_kernel<<<BATCH, 256, SM_OUT>>>(x, out);
}

// round 12
// speedup vs baseline: 1.3563x; 1.1938x over previous
#include <cuda_runtime.h>
#include <math.h>
#include <stdint.h>

#define BATCH 8192
#define NN 4096
#define LDB 68           // padded stride (floats), float4-aligned
#define EPSF 1e-8f
#define SKIP_TAU 1e-6f
#define TAU2 (SKIP_TAU * SKIP_TAU)

#define K0_BLOCKS 256
#define K0_NB 32
#define K2_BLOCKS 2048   // x4 matrices per block (2 per 128-thread group)
#define RT1_BLOCKS 256   // reduce_t stage-1 blocks (32 matrices each)
#define SWEEPS_BATCH 7
#define SWEEPS_SMALL 8

// ---------------- device scratch ----------------
__device__ __align__(256) float g_partial_mean[(size_t)RT1_BLOCKS * NN];
__device__ __align__(256) float g_mean[NN];
__device__ __align__(256) float g_s[NN];
__device__ __align__(256) float g_si[NN];
__device__ __align__(256) float g_gsqrt[NN];
__device__ __align__(256) float g_W[NN];
__device__ __align__(256) float g_WT[NN];
__device__ __align__(256) float g_partial_t[(size_t)BATCH * NN];
__device__ __align__(256) float g_tmean[NN];

// ---------------- packed f32x2 helpers ----------------
typedef unsigned long long u64;
__device__ __forceinline__ u64 pk2(float x, float y) {
    u64 r; asm("mov.b64 %0,{%1,%2};" : "=l"(r) : "f"(x), "f"(y)); return r;
}
__device__ __forceinline__ void up2(u64 v, float& x, float& y) {
    asm("mov.b64 {%0,%1},%2;" : "=f"(x), "=f"(y) : "l"(v));
}
__device__ __forceinline__ u64 fma2(u64 a, u64 b, u64 c) {
    u64 d; asm("fma.rn.f32x2 %0,%1,%2,%3;" : "=l"(d) : "l"(a), "l"(b), "l"(c)); return d;
}
__device__ __forceinline__ u64 mul2(u64 a, u64 b) {
    u64 d; asm("mul.rn.f32x2 %0,%1,%2;" : "=l"(d) : "l"(a), "l"(b)); return d;
}
__device__ __forceinline__ void barg(int id) {
    asm volatile("bar.sync %0, 128;" :: "r"(id) : "memory");
}

// ---------------- 256-thread helpers (side kernels) ----------------
__device__ __forceinline__ void load_tile(const float* __restrict__ g, float* __restrict__ s) {
    for (int i = threadIdx.x; i < 1024; i += 256) {
        int r = i >> 4, c4 = (i & 15) << 2;
        *(float4*)&s[r * LDB + c4] = *(const float4*)&g[(r << 6) + c4];
    }
}
__device__ __forceinline__ void store_tile(const float* __restrict__ s, float* __restrict__ g) {
    for (int i = threadIdx.x; i < 1024; i += 256) {
        int r = i >> 4, c4 = (i & 15) << 2;
        *(float4*)&g[(r << 6) + c4] = *(const float4*)&s[r * LDB + c4];
    }
}

__device__ __forceinline__ void mm64_t4(const float* __restrict__ A, const float* __restrict__ B,
                                        float* __restrict__ C, int cstride) {
    const int r0 = (threadIdx.x >> 4) << 2;
    const int c0 = (threadIdx.x & 15) << 2;
    u64 acc[8];
#pragma unroll
    for (int i = 0; i < 8; ++i) acc[i] = 0ull;
#pragma unroll 4
    for (int k = 0; k < 64; ++k) {
        float a0 = A[r0 * LDB + k],       a1 = A[(r0 + 1) * LDB + k];
        float a2 = A[(r0 + 2) * LDB + k], a3 = A[(r0 + 3) * LDB + k];
        ulonglong2 b = *(const ulonglong2*)&B[k * LDB + c0];
        u64 p;
        p = pk2(a0, a0); acc[0] = fma2(p, b.x, acc[0]); acc[1] = fma2(p, b.y, acc[1]);
        p = pk2(a1, a1); acc[2] = fma2(p, b.x, acc[2]); acc[3] = fma2(p, b.y, acc[3]);
        p = pk2(a2, a2); acc[4] = fma2(p, b.x, acc[4]); acc[5] = fma2(p, b.y, acc[5]);
        p = pk2(a3, a3); acc[6] = fma2(p, b.x, acc[6]); acc[7] = fma2(p, b.y, acc[7]);
    }
#pragma unroll
    for (int i = 0; i < 4; ++i)
        *(ulonglong2*)&C[(r0 + i) * cstride + c0] = make_ulonglong2(acc[2 * i], acc[2 * i + 1]);
}

__device__ __forceinline__ void gram_t4(const float* __restrict__ Bs, const float* __restrict__ B,
                                        float* __restrict__ out, int ostride) {
    const int r0 = (threadIdx.x >> 4) << 2;
    const int c0 = (threadIdx.x & 15) << 2;
    u64 acc[8];
#pragma unroll
    for (int i = 0; i < 8; ++i) acc[i] = 0ull;
#pragma unroll 4
    for (int j = 0; j < 64; ++j) {
        float4 u = *(const float4*)&Bs[j * LDB + r0];
        ulonglong2 b = *(const ulonglong2*)&B[j * LDB + c0];
        u64 p;
        p = pk2(u.x, u.x); acc[0] = fma2(p, b.x, acc[0]); acc[1] = fma2(p, b.y, acc[1]);
        p = pk2(u.y, u.y); acc[2] = fma2(p, b.x, acc[2]); acc[3] = fma2(p, b.y, acc[3]);
        p = pk2(u.z, u.z); acc[4] = fma2(p, b.x, acc[4]); acc[5] = fma2(p, b.y, acc[5]);
        p = pk2(u.w, u.w); acc[6] = fma2(p, b.x, acc[6]); acc[7] = fma2(p, b.y, acc[7]);
    }
#pragma unroll
    for (int i = 0; i < 4; ++i)
        *(ulonglong2*)&out[(r0 + i) * ostride + c0] = make_ulonglong2(acc[2 * i], acc[2 * i + 1]);
}

__device__ __forceinline__ float colnrm2(const float* __restrict__ B, int j, int seg, float4 v[4]) {
    const float4* c = (const float4*)(B + j * LDB + (seg << 4));
    v[0] = c[0]; v[1] = c[1]; v[2] = c[2]; v[3] = c[3];
    float n = v[0].x * v[0].x;
    n = fmaf(v[0].y, v[0].y, n); n = fmaf(v[0].z, v[0].z, n); n = fmaf(v[0].w, v[0].w, n);
    n = fmaf(v[1].x, v[1].x, n); n = fmaf(v[1].y, v[1].y, n); n = fmaf(v[1].z, v[1].z, n); n = fmaf(v[1].w, v[1].w, n);
    n = fmaf(v[2].x, v[2].x, n); n = fmaf(v[2].y, v[2].y, n); n = fmaf(v[2].z, v[2].z, n); n = fmaf(v[2].w, v[2].w, n);
    n = fmaf(v[3].x, v[3].x, n); n = fmaf(v[3].y, v[3].y, n); n = fmaf(v[3].z, v[3].z, n); n = fmaf(v[3].w, v[3].w, n);
    n += __shfl_xor_sync(0xffffffffu, n, 1);
    n += __shfl_xor_sync(0xffffffffu, n, 2);
    return n;
}

__device__ __forceinline__ void scale_store(float* __restrict__ D, int j, int seg,
                                            const float4 v[4], float f) {
    float4* d = (float4*)(D + j * LDB + (seg << 4));
    d[0] = make_float4(f * v[0].x, f * v[0].y, f * v[0].z, f * v[0].w);
    d[1] = make_float4(f * v[1].x, f * v[1].y, f * v[1].z, f * v[1].w);
    d[2] = make_float4(f * v[2].x, f * v[2].y, f * v[2].z, f * v[2].w);
    d[3] = make_float4(f * v[3].x, f * v[3].y, f * v[3].z, f * v[3].w);
}

// ---------------- smem rot step (side kernels only) ----------------
__device__ __forceinline__ void rot_step(float* __restrict__ B, float* __restrict__ nbuf,
                                         int p, int q, int o0, int o1, int lt) {
    float* bp = B + p * LDB;
    float* bq = B + q * LDB;
    ulonglong2 P0 = *(ulonglong2*)(bp + o0), P1 = *(ulonglong2*)(bp + o1);
    ulonglong2 Q0 = *(ulonglong2*)(bq + o0), Q1 = *(ulonglong2*)(bq + o1);
    u64 spq = mul2(P0.x, Q0.x);
    spq = fma2(P0.y, Q0.y, spq); spq = fma2(P1.x, Q1.x, spq); spq = fma2(P1.y, Q1.y, spq);
    float a0, a1;
    up2(spq, a0, a1);
    float apq = a0 + a1;
    apq += __shfl_xor_sync(0xffffffffu, apq, 1);
    apq += __shfl_xor_sync(0xffffffffu, apq, 2);
    apq += __shfl_xor_sync(0xffffffffu, apq, 4);
    float app = nbuf[p], aqq = nbuf[q];
    if (apq * apq > TAU2 * app * aqq) {
        float zeta = (aqq - app) / (2.0f * apq);
        float t = copysignf(1.0f, zeta) / (fabsf(zeta) + sqrtf(fmaf(zeta, zeta, 1.0f)));
        float c = rsqrtf(fmaf(t, t, 1.0f));
        float s = t * c;
        u64 c2 = pk2(c, c), s2 = pk2(s, s), ns2 = pk2(-s, -s);
        ulonglong2 NP0, NP1, NQ0, NQ1;
        NP0.x = fma2(c2, P0.x, mul2(ns2, Q0.x));
        NP0.y = fma2(c2, P0.y, mul2(ns2, Q0.y));
        NP1.x = fma2(c2, P1.x, mul2(ns2, Q1.x));
        NP1.y = fma2(c2, P1.y, mul2(ns2, Q1.y));
        NQ0.x = fma2(s2, P0.x, mul2(c2, Q0.x));
        NQ0.y = fma2(s2, P0.y, mul2(c2, Q0.y));
        NQ1.x = fma2(s2, P1.x, mul2(c2, Q1.x));
        NQ1.y = fma2(s2, P1.y, mul2(c2, Q1.y));
        *(ulonglong2*)(bp + o0) = NP0; *(ulonglong2*)(bp + o1) = NP1;
        *(ulonglong2*)(bq + o0) = NQ0; *(ulonglong2*)(bq + o1) = NQ1;
        if ((lt & 7) == 0) {
            float d = t * apq;
            nbuf[p] = app - d;
            nbuf[q] = aqq + d;
        }
    }
}

__device__ void jacobi_onesided(float* __restrict__ B, float* __restrict__ nbuf, int sweeps) {
    const int tid = threadIdx.x;
    const int k = tid >> 3;
    const int o0 = (tid & 7) << 2;
    const int o1 = 32 + o0;
    const int jn = tid >> 2, segn = tid & 3;
    for (int sw = 0; sw < sweeps; ++sw) {
        {
            float4 v[4];
            float n = colnrm2(B, jn, segn, v);
            if (segn == 0) nbuf[jn] = n;
        }
        __syncthreads();
        int p = (k == 0) ? 0 : k;
        int q = 63 - k;
        for (int rr = 0; rr < 63; ++rr) {
            rot_step(B, nbuf, p, q, o0, o1, tid);
            if (k) p = (p == 63) ? 1 : p + 1;
            q = (q == 63) ? 1 : q + 1;
            __syncthreads();
        }
    }
}

// ---------------- register pair rotation with always-swap ----------------
// U holds position a, V holds position b (a<b). After: U <- v' (rot), V <- u'.
// Norms travel with the data. Skip still swaps (ordering requires it).
__device__ __forceinline__ void rotpair(u64 U[4], u64 V[4], float& nu, float& nv, unsigned omask) {
    u64 d = mul2(U[0], V[0]);
    d = fma2(U[1], V[1], d);
    d = fma2(U[2], V[2], d);
    d = fma2(U[3], V[3], d);
    float a0, a1; up2(d, a0, a1);
    float apq = a0 + a1;
    apq += __shfl_xor_sync(omask, apq, 1);
    apq += __shfl_xor_sync(omask, apq, 2);
    apq += __shfl_xor_sync(omask, apq, 4);
    if (apq * apq > TAU2 * nu * nv) {
        float zeta = (nv - nu) / (2.0f * apq);
        float t = copysignf(1.0f, zeta) / (fabsf(zeta) + sqrtf(fmaf(zeta, zeta, 1.0f)));
        float c = rsqrtf(fmaf(t, t, 1.0f));
        float s = t * c;
        u64 c2 = pk2(c, c), s2 = pk2(s, s), ns2 = pk2(-s, -s);
#pragma unroll
        for (int i = 0; i < 4; ++i) {
            u64 vp = fma2(s2, U[i], mul2(c2, V[i]));   // v' = s*u + c*v
            u64 up = fma2(c2, U[i], mul2(ns2, V[i]));  // u' = c*u - s*v
            U[i] = vp; V[i] = up;
        }
        float dd = t * apq;
        float a = nu - dd;   // norm of u'
        nu = nv + dd;        // U holds v'
        nv = a;
    } else {
#pragma unroll
        for (int i = 0; i < 4; ++i) { u64 tmp = U[i]; U[i] = V[i]; V[i] = tmp; }
        float tn = nu; nu = nv; nv = tn;
    }
}

// ---------------- 128-thread in-place matmuls (from round 11) ----------------
__device__ __forceinline__ void mmip_left(const float* __restrict__ A, float* __restrict__ X,
                                          int gt, int bid) {
    const int r0 = (gt >> 3) << 2;
    const int cc = (gt & 7) << 2;
#pragma unroll
    for (int cb = 0; cb < 2; ++cb) {
        const int c0 = (cb << 5) + cc;
        u64 acc[8];
#pragma unroll
        for (int i = 0; i < 8; ++i) acc[i] = 0ull;
#pragma unroll 4
        for (int k = 0; k < 64; ++k) {
            float a0 = A[r0 * LDB + k],       a1 = A[(r0 + 1) * LDB + k];
            float a2 = A[(r0 + 2) * LDB + k], a3 = A[(r0 + 3) * LDB + k];
            ulonglong2 b = *(const ulonglong2*)&X[k * LDB + c0];
            u64 p;
            p = pk2(a0, a0); acc[0] = fma2(p, b.x, acc[0]); acc[1] = fma2(p, b.y, acc[1]);
            p = pk2(a1, a1); acc[2] = fma2(p, b.x, acc[2]); acc[3] = fma2(p, b.y, acc[3]);
            p = pk2(a2, a2); acc[4] = fma2(p, b.x, acc[4]); acc[5] = fma2(p, b.y, acc[5]);
            p = pk2(a3, a3); acc[6] = fma2(p, b.x, acc[6]); acc[7] = fma2(p, b.y, acc[7]);
        }
        barg(bid);
#pragma unroll
        for (int i = 0; i < 4; ++i)
            *(ulonglong2*)&X[(r0 + i) * LDB + c0] = make_ulonglong2(acc[2 * i], acc[2 * i + 1]);
        barg(bid);
    }
}

__device__ __forceinline__ void mmip_right(float* __restrict__ X, const float* __restrict__ B,
                                           int gt, int bid) {
    const int rr = (gt >> 4) << 2;
    const int c0 = (gt & 15) << 2;
#pragma unroll
    for (int rb = 0; rb < 2; ++rb) {
        const int r0 = (rb << 5) + rr;
        u64 acc[8];
#pragma unroll
        for (int i = 0; i < 8; ++i) acc[i] = 0ull;
#pragma unroll 4
        for (int k = 0; k < 64; ++k) {
            float a0 = X[r0 * LDB + k],       a1 = X[(r0 + 1) * LDB + k];
            float a2 = X[(r0 + 2) * LDB + k], a3 = X[(r0 + 3) * LDB + k];
            ulonglong2 b = *(const ulonglong2*)&B[k * LDB + c0];
            u64 p;
            p = pk2(a0, a0); acc[0] = fma2(p, b.x, acc[0]); acc[1] = fma2(p, b.y, acc[1]);
            p = pk2(a1, a1); acc[2] = fma2(p, b.x, acc[2]); acc[3] = fma2(p, b.y, acc[3]);
            p = pk2(a2, a2); acc[4] = fma2(p, b.x, acc[4]); acc[5] = fma2(p, b.y, acc[5]);
            p = pk2(a3, a3); acc[6] = fma2(p, b.x, acc[6]); acc[7] = fma2(p, b.y, acc[7]);
        }
        barg(bid);
#pragma unroll
        for (int i = 0; i < 4; ++i)
            *(ulonglong2*)&X[(r0 + i) * LDB + c0] = make_ulonglong2(acc[2 * i], acc[2 * i + 1]);
        barg(bid);
    }
}

__device__ __forceinline__ void gram_g(const float* __restrict__ B, const float* __restrict__ fb,
                                       float* __restrict__ out, int gt) {
    const int c0 = (gt & 15) << 2;
    const int rbase = (gt >> 4) << 3;
#pragma unroll
    for (int half = 0; half < 2; ++half) {
        const int r0 = rbase + (half << 2);
        u64 acc[8];
#pragma unroll
        for (int i = 0; i < 8; ++i) acc[i] = 0ull;
#pragma unroll 4
        for (int j = 0; j < 64; ++j) {
            float f = fb[j];
            float4 u = *(const float4*)&B[j * LDB + r0];
            ulonglong2 b = *(const ulonglong2*)&B[j * LDB + c0];
            u64 p;
            p = pk2(f * u.x, f * u.x); acc[0] = fma2(p, b.x, acc[0]); acc[1] = fma2(p, b.y, acc[1]);
            p = pk2(f * u.y, f * u.y); acc[2] = fma2(p, b.x, acc[2]); acc[3] = fma2(p, b.y, acc[3]);
            p = pk2(f * u.z, f * u.z); acc[4] = fma2(p, b.x, acc[4]); acc[5] = fma2(p, b.y, acc[5]);
            p = pk2(f * u.w, f * u.w); acc[6] = fma2(p, b.x, acc[6]); acc[7] = fma2(p, b.y, acc[7]);
        }
#pragma unroll
        for (int i = 0; i < 4; ++i)
            *(ulonglong2*)&out[(r0 + i) * 64 + c0] = make_ulonglong2(acc[2 * i], acc[2 * i + 1]);
    }
}

// ---------------- kernel 0: arithmetic mean ----------------
__global__ __launch_bounds__(256) void mean_partial_kernel(const float* __restrict__ x) {
    const int g = blockIdx.x, tid = threadIdx.x;
    float4 acc[4] = {{0,0,0,0},{0,0,0,0},{0,0,0,0},{0,0,0,0}};
    const float4* xb = (const float4*)(x + (size_t)g * K0_NB * NN);
    for (int b = 0; b < K0_NB; ++b) {
#pragma unroll
        for (int i = 0; i < 4; ++i) {
            float4 v = xb[(size_t)b * 1024 + tid + (i << 8)];
            acc[i].x += v.x; acc[i].y += v.y; acc[i].z += v.z; acc[i].w += v.w;
        }
    }
    float4* pm = (float4*)(g_partial_mean + (size_t)g * NN);
#pragma unroll
    for (int i = 0; i < 4; ++i) pm[tid + (i << 8)] = acc[i];
}

__global__ void reduce_mean_kernel() {
    int j = blockIdx.x * 128 + threadIdx.x;
    float acc = 0.f;
    for (int g = 0; g < K0_BLOCKS; ++g) acc += g_partial_mean[(size_t)g * NN + j];
    g_mean[j] = acc * (1.0f / BATCH);
}

// ---------------- kernel 1: eigh(mean)->s,si ; eigh(G)->gsqrt ----------------
__global__ __launch_bounds__(256) void prep_kernel(const float* __restrict__ G) {
    extern __shared__ float sm[];
    float* A    = sm;
    float* Bsc  = A + 4352;
    float* nbuf = Bsc + 4352;
    const int tid = threadIdx.x;
    load_tile(blockIdx.x == 0 ? g_mean : G, A);
    __syncthreads();
    jacobi_onesided(A, nbuf, SWEEPS_SMALL);
    const int j = tid >> 2, seg = tid & 3;
    float4 v[4];
    float n = colnrm2(A, j, seg, v);
    float lam = fmaxf(sqrtf(n), EPSF);
    float inv_n = 1.0f / n;
    scale_store(Bsc, j, seg, v, sqrtf(lam) * inv_n);
    __syncthreads();
    gram_t4(Bsc, A, blockIdx.x == 0 ? g_s : g_gsqrt, 64);
    if (blockIdx.x == 0) {
        __syncthreads();
        scale_store(Bsc, j, seg, v, rsqrtf(lam) * inv_n);
        __syncthreads();
        gram_t4(Bsc, A, g_si, 64);
    }
}

// ---------------- kernel 2: logm via register-resident odd-even Jacobi ----------------
__global__ __launch_bounds__(256, 3) void batch_log_kernel(const float* __restrict__ x) {
    extern __shared__ float sm[];
    float* T0 = sm;                       // si (shared, read-only)
    const int tid = threadIdx.x;
    const int g = tid >> 7;
    const int gt = tid & 127;
    const int bid = g + 1;
    float* T  = sm + 4352 + g * 4352;
    float* fb = sm + 3 * 4352 + g * 64;

    load_tile(g_si, T0);
    __syncthreads();                      // only block-wide barrier

    const int o  = gt >> 3;               // octet 0..15, positions 4o..4o+3
    const int o0 = (gt & 7) << 2;
    const int o1 = 32 + o0;
    const unsigned omask = 0xFFu << ((tid & 31) & ~7u);
    // exchange buffers inside T (dead during Jacobi)
    float* xcol = T;                      // 16 * 68
    float* ycol = T + 1088;               // 16 * 68
    float* xn   = T + 2176;               // 16
    float* yn   = T + 2192;               // 16

    for (int mi = 0; mi < 2; ++mi) {
        const size_t mat = (size_t)blockIdx.x * 4 + g * 2 + mi;
        const float* xb = x + mat * NN;
        for (int i = gt; i < 1024; i += 128) {
            int r = i >> 4, c4 = (i & 15) << 2;
            *(float4*)&T[r * LDB + c4] = *(const float4*)&xb[(r << 6) + c4];
        }
        barg(bid);
        mmip_left(T0, T, gt, bid);        // T = si @ x
        mmip_right(T, T0, gt, bid);       // T = T @ si

        // load 4 columns into registers
        u64 C[4][4];
        float nrm[4];
#pragma unroll
        for (int c = 0; c < 4; ++c) {
            const float* base = T + (4 * o + c) * LDB;
            ulonglong2 t0 = *(const ulonglong2*)(base + o0);
            ulonglong2 t1 = *(const ulonglong2*)(base + o1);
            C[c][0] = t0.x; C[c][1] = t0.y; C[c][2] = t1.x; C[c][3] = t1.y;
        }
        barg(bid);                        // T reads done; exchange area live

        for (int sw = 0; sw < SWEEPS_BATCH; ++sw) {
            // refresh norms (registers only)
#pragma unroll
            for (int c = 0; c < 4; ++c) {
                u64 d = mul2(C[c][0], C[c][0]);
                d = fma2(C[c][1], C[c][1], d);
                d = fma2(C[c][2], C[c][2], d);
                d = fma2(C[c][3], C[c][3], d);
                float a0, a1; up2(d, a0, a1);
                float n = a0 + a1;
                n += __shfl_xor_sync(omask, n, 1);
                n += __shfl_xor_sync(omask, n, 2);
                n += __shfl_xor_sync(omask, n, 4);
                nrm[c] = n;
            }
            for (int r = 0; r < 32; ++r) {
                // odd round: local pairs (C0,C1), (C2,C3)
                rotpair(C[0], C[1], nrm[0], nrm[1], omask);
                rotpair(C[2], C[3], nrm[2], nrm[3], omask);
                // publish C0 for left neighbor's cross pair
                *(ulonglong2*)(xcol + o * 68 + o0) = make_ulonglong2(C[0][0], C[0][1]);
                *(ulonglong2*)(xcol + o * 68 + o1) = make_ulonglong2(C[0][2], C[0][3]);
                if ((gt & 7) == 0) xn[o] = nrm[0];
                // even round internal pair (C1,C2) — overlap with exchange
                rotpair(C[1], C[2], nrm[1], nrm[2], omask);
                barg(bid);
                if (o < 15) {             // cross pair (C3, neighbor C0)
                    u64 D[4];
                    ulonglong2 t0 = *(const ulonglong2*)(xcol + (o + 1) * 68 + o0);
                    ulonglong2 t1 = *(const ulonglong2*)(xcol + (o + 1) * 68 + o1);
                    D[0] = t0.x; D[1] = t0.y; D[2] = t1.x; D[3] = t1.y;
                    float nD = xn[o + 1];
                    rotpair(C[3], D, nrm[3], nD, omask);
                    *(ulonglong2*)(ycol + (o + 1) * 68 + o0) = make_ulonglong2(D[0], D[1]);
                    *(ulonglong2*)(ycol + (o + 1) * 68 + o1) = make_ulonglong2(D[2], D[3]);
                    if ((gt & 7) == 0) yn[o + 1] = nD;
                }
                barg(bid);
                if (o > 0) {              // receive new C0 (position 4o)
                    ulonglong2 t0 = *(const ulonglong2*)(ycol + o * 68 + o0);
                    ulonglong2 t1 = *(const ulonglong2*)(ycol + o * 68 + o1);
                    C[0][0] = t0.x; C[0][1] = t0.y; C[0][2] = t1.x; C[0][3] = t1.y;
                    nrm[0] = yn[o];
                }
            }
        }
        barg(bid);                        // exchange reads done before T overwrite

        // epilogue: exact norms, log factors, store columns back to T
#pragma unroll
        for (int c = 0; c < 4; ++c) {
            u64 d = mul2(C[c][0], C[c][0]);
            d = fma2(C[c][1], C[c][1], d);
            d = fma2(C[c][2], C[c][2], d);
            d = fma2(C[c][3], C[c][3], d);
            float a0, a1; up2(d, a0, a1);
            float n = a0 + a1;
            n += __shfl_xor_sync(omask, n, 1);
            n += __shfl_xor_sync(omask, n, 2);
            n += __shfl_xor_sync(omask, n, 4);
            float* base = T + (4 * o + c) * LDB;
            *(ulonglong2*)(base + o0) = make_ulonglong2(C[c][0], C[c][1]);
            *(ulonglong2*)(base + o1) = make_ulonglong2(C[c][2], C[c][3]);
            if ((gt & 7) == 0) fb[4 * o + c] = logf(fmaxf(sqrtf(n), EPSF)) / n;
        }
        barg(bid);
        gram_g(T, fb, g_partial_t + mat * NN, gt);
        barg(bid);
    }
}

// ---------------- reduce_t: two-stage vectorized ----------------
__global__ __launch_bounds__(256) void reduce_t1_kernel() {
    const int g = blockIdx.x, tid = threadIdx.x;
    float4 acc[4] = {{0,0,0,0},{0,0,0,0},{0,0,0,0},{0,0,0,0}};
    const float4* src = (const float4*)(g_partial_t + (size_t)g * 32 * NN);
    for (int b = 0; b < 32; ++b) {
#pragma unroll
        for (int i = 0; i < 4; ++i) {
            float4 v = src[(size_t)b * 1024 + tid + (i << 8)];
            acc[i].x += v.x; acc[i].y += v.y; acc[i].z += v.z; acc[i].w += v.w;
        }
    }
    float4* pm = (float4*)(g_partial_mean + (size_t)g * NN);
#pragma unroll
    for (int i = 0; i < 4; ++i) pm[tid + (i << 8)] = acc[i];
}

__global__ void reduce_t2_kernel() {
    int j = blockIdx.x * 128 + threadIdx.x;
    float acc = 0.f;
    for (int g = 0; g < RT1_BLOCKS; ++g) acc += g_partial_mean[(size_t)g * NN + j];
    g_tmean[j] = acc * (1.0f / BATCH);
}

// ---------------- kernel 3: expm(tmean) via shifted one-sided, center, csi, W, WT ----------------
__global__ __launch_bounds__(256) void center_kernel() {
    extern __shared__ float sm[];
    float* A    = sm;
    float* T1   = A + 4352;
    float* T2   = T1 + 4352;
    float* fw   = T2 + 4352;
    float* nbuf = fw + 64;
    float* sigp = nbuf + 64;
    const int tid = threadIdx.x;
    const int j = tid >> 2, seg = tid & 3;

    load_tile(g_tmean, A);
    __syncthreads();
    {
        const float4* c = (const float4*)(A + j * LDB + (seg << 4));
        float s = 0.f;
#pragma unroll
        for (int i = 0; i < 4; ++i) {
            float4 v = c[i];
            s += fabsf(v.x) + fabsf(v.y) + fabsf(v.z) + fabsf(v.w);
        }
        s += __shfl_xor_sync(0xffffffffu, s, 1);
        s += __shfl_xor_sync(0xffffffffu, s, 2);
        if (seg == 0) fw[j] = s;
    }
    __syncthreads();
    if (tid == 0) {
        float mx = 0.f;
        for (int i = 0; i < 64; ++i) mx = fmaxf(mx, fw[i]);
        sigp[0] = 1.1f * mx + 1e-2f;
    }
    __syncthreads();
    const float sigma = sigp[0];
    if (tid < 64) A[tid * LDB + tid] += sigma;
    __syncthreads();
    jacobi_onesided(A, nbuf, SWEEPS_SMALL);
    {
        float4 v[4];
        float n = colnrm2(A, j, seg, v);
        float mu = fmaxf(sqrtf(n), EPSF);
        float f = expf(mu - sigma) / n;
        scale_store(T1, j, seg, v, f);
    }
    __syncthreads();
    gram_t4(T1, A, T2, LDB);
    __syncthreads();
    load_tile(g_s, A);
    __syncthreads();
    mm64_t4(A, T2, T1, LDB);  __syncthreads();
    mm64_t4(T1, A, T2, LDB);  __syncthreads();
    jacobi_onesided(T2, nbuf, SWEEPS_SMALL);
    {
        float4 v[4];
        float n = colnrm2(T2, j, seg, v);
        float lam = fmaxf(sqrtf(n), EPSF);
        float f = rsqrtf(lam) / n;
        scale_store(T1, j, seg, v, f);
    }
    __syncthreads();
    gram_t4(T1, T2, A, LDB);
    __syncthreads();
    load_tile(g_gsqrt, T1);
    __syncthreads();
    mm64_t4(T1, A, T2, LDB);
    __syncthreads();
    store_tile(T2, g_W);
    for (int idx = tid; idx < NN; idx += 256) {
        int rr = idx >> 6, cc = idx & 63;
        g_WT[(cc << 6) + rr] = T2[rr * LDB + cc];
    }
}

// ---------------- kernel 4: out_b = W x_b W^T ----------------
__global__ __launch_bounds__(256) void output_kernel(const float* __restrict__ x,
                                                     float* __restrict__ out) {
    extern __shared__ float sm[];
    float* Ws = sm;
    float* WT = Ws + 4352;
    float* xs = WT + 4352;
    float* P  = xs + 4352;
    load_tile(g_W, Ws);
    load_tile(g_WT, WT);
    load_tile(x + (size_t)blockIdx.x * NN, xs);
    __syncthreads();
    mm64_t4(Ws, xs, P, LDB);
    __syncthreads();
    mm64_t4(P, WT, out + (size_t)blockIdx.x * NN, 64);
}

// ---------------- launcher ----------------
extern "C" void kernel_launch(void* const* d_in, const int* in_sizes, int n_in,
                              void* d_out, int out_size) {
    const float* x;
    const float* G;
    if (in_sizes[0] == NN) { G = (const float*)d_in[0]; x = (const float*)d_in[1]; }
    else                   { x = (const float*)d_in[0]; G = (const float*)d_in[1]; }
    float* out = (float*)d_out;

    constexpr size_t SM_PREP   = (size_t)(2 * 4352 + 64) * 4;
    constexpr size_t SM_BATCH  = (size_t)(3 * 4352 + 128) * 4;
    constexpr size_t SM_CENTER = (size_t)(3 * 4352 + 64 + 64 + 4) * 4;
    constexpr size_t SM_OUT    = (size_t)(4 * 4352) * 4;

    cudaFuncSetAttribute(batch_log_kernel, cudaFuncAttributeMaxDynamicSharedMemorySize, (int)SM_BATCH);
    cudaFuncSetAttribute(center_kernel,    cudaFuncAttributeMaxDynamicSharedMemorySize, (int)SM_CENTER);
    cudaFuncSetAttribute(output_kernel,    cudaFuncAttributeMaxDynamicSharedMemorySize, (int)SM_OUT);

    mean_partial_kernel<<<K0_BLOCKS, 256>>>(x);
    reduce_mean_kernel<<<32, 128>>>();
    prep_kernel<<<2, 256, SM_PREP>>>(G);
    batch_log_kernel<<<K2_BLOCKS, 256, SM_BATCH>>>(x);
    reduce_t1_kernel<<<RT1_BLOCKS, 256>>>();
    reduce_t2_kernel<<<32, 128>>>();
    center_kernel<<<1, 256, SM_CENTER>>>();
    output_kernel<<<BATCH, 256, SM_OUT>>>(x, out);
}